// round 1
// baseline (speedup 1.0000x reference)
#include <cuda_runtime.h>
#include <cuda_bf16.h>

// ---------------- problem constants ----------------
constexpr int NB     = 64;     // batches
constexpr int NODES_ = 116;    // nodes per batch
constexpr int Nn     = NB * NODES_;   // 7424
constexpr int Tt     = 256;
constexpr int Hh     = 32;
constexpr int Ee     = Nn * 128;      // 950272
constexpr int HID    = 64;

// ---------------- device scratch (no cudaMalloc allowed) ----------------
__device__ __align__(16) float d_xT[Tt * Nn];     // transposed x
__device__ __align__(16) float d_gruH[Nn * Hh];   // GRU output
__device__ __align__(16) float d_xw[Nn * HID];    // per-layer h @ W^T
__device__ __align__(16) float d_hbuf[Nn * HID];  // per-layer output
__device__ float d_deg[Nn];
__device__ float d_dis[Nn];
__device__ float d_dis2[Nn];
__device__ int   d_cnt[Nn];
__device__ int   d_rowptr[Nn + 1];
__device__ int   d_cursor[Nn];
__device__ int   d_csrc[Ee];
__device__ __align__(16) float d_ccoef[Ee];

// ---------------- helpers ----------------
__device__ __forceinline__ float sigm_(float a) {
    return __fdividef(1.0f, 1.0f + __expf(-a));
}
__device__ __forceinline__ float tanh_(float a) {
    // tanh(x) = 1 - 2/(1+exp(2x)); saturates correctly at +-inf
    return fmaf(-2.0f, __fdividef(1.0f, 1.0f + __expf(2.0f * a)), 1.0f);
}

// ---------------- 1) transpose x: [N][T] -> [T][N] ----------------
__global__ void transpose_x_kernel(const float* __restrict__ x, float* __restrict__ xT) {
    __shared__ float tile[32][33];
    int bn = blockIdx.x * 32;
    int bt = blockIdx.y * 32;
    int tx = threadIdx.x, ty = threadIdx.y; // (32, 8)
    #pragma unroll
    for (int j = 0; j < 32; j += 8)
        tile[ty + j][tx] = x[(bn + ty + j) * Tt + (bt + tx)];
    __syncthreads();
    #pragma unroll
    for (int j = 0; j < 32; j += 8)
        xT[(bt + ty + j) * Nn + (bn + tx)] = tile[tx][ty + j];
}

// ---------------- 2) init deg/cnt ----------------
__global__ void init_kernel(float* __restrict__ deg, int* __restrict__ cnt) {
    int i = blockIdx.x * 256 + threadIdx.x;
    if (i < Nn) { deg[i] = 1.0f; cnt[i] = 0; }
}

// ---------------- 3) degree + in-count histogram ----------------
__global__ void edge_deg_kernel(const int* __restrict__ ei, const float* __restrict__ ea,
                                float* __restrict__ deg, int* __restrict__ cnt) {
    int e = blockIdx.x * 256 + threadIdx.x;
    if (e >= Ee) return;
    int dst = ei[Ee + e];
    atomicAdd(&deg[dst], ea[e]);
    atomicAdd(&cnt[dst], 1);
}

// ---------------- 4) single-block scan -> rowptr/cursor, plus dis/dis2 ----------------
__global__ void scan_kernel(const int* __restrict__ cnt, const float* __restrict__ deg,
                            int* __restrict__ rowptr, int* __restrict__ cursor,
                            float* __restrict__ dis, float* __restrict__ dis2) {
    __shared__ int ssum[1024];
    const int C = 8; // 1024*8 = 8192 >= Nn
    int tid = threadIdx.x;
    int base = tid * C;
    int loc[C];
    int s = 0;
    #pragma unroll
    for (int j = 0; j < C; j++) {
        int idx = base + j;
        int v = (idx < Nn) ? cnt[idx] : 0;
        loc[j] = s;
        s += v;
    }
    ssum[tid] = s;
    __syncthreads();
    for (int off = 1; off < 1024; off <<= 1) {
        int add = (tid >= off) ? ssum[tid - off] : 0;
        __syncthreads();
        ssum[tid] += add;
        __syncthreads();
    }
    int pre = (tid > 0) ? ssum[tid - 1] : 0;
    #pragma unroll
    for (int j = 0; j < C; j++) {
        int idx = base + j;
        if (idx < Nn) {
            int v = pre + loc[j];
            rowptr[idx] = v;
            cursor[idx] = v;
        }
    }
    if (tid == 1023) rowptr[Nn] = ssum[1023];
    for (int i = tid; i < Nn; i += 1024) {
        float dg = deg[i];
        float di = rsqrtf(dg);
        dis[i]  = di;
        dis2[i] = di * di;
    }
}

// ---------------- 5) CSR fill (by dst) with precomputed coef ----------------
__global__ void csr_fill_kernel(const int* __restrict__ ei, const float* __restrict__ ea,
                                const float* __restrict__ dis, int* __restrict__ cursor,
                                int* __restrict__ csrc, float* __restrict__ ccoef) {
    int e = blockIdx.x * 256 + threadIdx.x;
    if (e >= Ee) return;
    int src = ei[e];
    int dst = ei[Ee + e];
    float c = dis[src] * ea[e] * dis[dst];
    int pos = atomicAdd(&cursor[dst], 1);
    csrc[pos]  = src;
    ccoef[pos] = c;
}

// ---------------- 6) GRU: 8 threads per node, each owns 4 hidden channels ----------------
__global__ void __launch_bounds__(64) gru_kernel(
    const float* __restrict__ xT, const int* __restrict__ lengths,
    const float* __restrict__ W_hh, const float* __restrict__ W_ih,
    const float* __restrict__ b_ih, const float* __restrict__ b_hh,
    float* __restrict__ out) {
    // shared: W_hh transposed -> sWT[k][row], row in [0,96)
    __shared__ __align__(16) float sWT[32 * 96];
    int tid = threadIdx.x;
    for (int i = tid; i < 32 * 96; i += 64) {
        int k = i / 96, row = i % 96;
        sWT[i] = W_hh[row * 32 + k];
    }
    __syncthreads();

    int gt   = blockIdx.x * 64 + tid;
    int node = gt >> 3;
    int q    = gt & 7;
    int lane = tid & 31;
    int gbase = lane & ~7;

    int len = lengths[node / NODES_];
    int wlen = len;
    #pragma unroll
    for (int off = 16; off > 0; off >>= 1)
        wlen = max(wlen, __shfl_xor_sync(0xffffffffu, wlen, off));

    int j0 = q * 4;
    float wiR[4], wiZ[4], wiN[4], bR[4], bZ[4], bNx[4], bNh[4];
    #pragma unroll
    for (int i = 0; i < 4; i++) {
        int j = j0 + i;
        wiR[i] = W_ih[j];
        wiZ[i] = W_ih[32 + j];
        wiN[i] = W_ih[64 + j];
        bR[i]  = b_ih[j] + b_hh[j];
        bZ[i]  = b_ih[32 + j] + b_hh[32 + j];
        bNx[i] = b_ih[64 + j];
        bNh[i] = b_hh[64 + j];
    }

    float h[4] = {0.f, 0.f, 0.f, 0.f};
    float xnext = xT[node];
    for (int t = 0; t < wlen; t++) {
        float xt = xnext;
        if (t + 1 < wlen) xnext = xT[(t + 1) * Nn + node];

        // gather full h vector from the 8 lanes of this node group
        float hall[32];
        #pragma unroll
        for (int m = 0; m < 8; m++) {
            #pragma unroll
            for (int i = 0; i < 4; i++)
                hall[m * 4 + i] = __shfl_sync(0xffffffffu, h[i], gbase + m);
        }

        float aR[4], aZ[4], aN[4];
        #pragma unroll
        for (int i = 0; i < 4; i++) {
            aR[i] = fmaf(xt, wiR[i], bR[i]);
            aZ[i] = fmaf(xt, wiZ[i], bZ[i]);
            aN[i] = bNh[i];
        }
        #pragma unroll
        for (int k = 0; k < 32; k++) {
            float hk = hall[k];
            const float* wb = &sWT[k * 96];
            float4 w0 = *(const float4*)(wb + j0);
            float4 w1 = *(const float4*)(wb + 32 + j0);
            float4 w2 = *(const float4*)(wb + 64 + j0);
            aR[0] = fmaf(hk, w0.x, aR[0]); aR[1] = fmaf(hk, w0.y, aR[1]);
            aR[2] = fmaf(hk, w0.z, aR[2]); aR[3] = fmaf(hk, w0.w, aR[3]);
            aZ[0] = fmaf(hk, w1.x, aZ[0]); aZ[1] = fmaf(hk, w1.y, aZ[1]);
            aZ[2] = fmaf(hk, w1.z, aZ[2]); aZ[3] = fmaf(hk, w1.w, aZ[3]);
            aN[0] = fmaf(hk, w2.x, aN[0]); aN[1] = fmaf(hk, w2.y, aN[1]);
            aN[2] = fmaf(hk, w2.z, aN[2]); aN[3] = fmaf(hk, w2.w, aN[3]);
        }
        bool upd = (t < len);
        #pragma unroll
        for (int i = 0; i < 4; i++) {
            float r  = sigm_(aR[i]);
            float z  = sigm_(aZ[i]);
            float nn = tanh_(fmaf(xt, wiN[i], bNx[i]) + r * aN[i]);
            float hnew = fmaf(z, h[i] - nn, nn);  // (1-z)*nn + z*h
            h[i] = upd ? hnew : h[i];
        }
    }
    #pragma unroll
    for (int i = 0; i < 4; i++)
        out[node * Hh + j0 + i] = h[i];
}

// ---------------- 7) GEMM: out[n][o] = sum_k in[n][k] * W[o][k] ----------------
template <int Kd>
__global__ void gemm_kernel(const float* __restrict__ in, const float* __restrict__ W,
                            float* __restrict__ out) {
    __shared__ float sW[Kd * 64]; // [k][o]
    __shared__ float sh[4 * Kd];
    int tid = threadIdx.x; // 256
    for (int i = tid; i < Kd * 64; i += 256) {
        int k = i >> 6, o = i & 63;
        sW[i] = W[o * Kd + k];
    }
    int nb = blockIdx.x * 4;
    for (int i = tid; i < 4 * Kd; i += 256)
        sh[i] = in[nb * Kd + i];
    __syncthreads();
    int ln = tid >> 6, o = tid & 63;
    float acc = 0.0f;
    #pragma unroll
    for (int k = 0; k < Kd; k++)
        acc = fmaf(sh[ln * Kd + k], sW[k * 64 + o], acc);
    out[(nb + ln) * 64 + o] = acc;
}

// ---------------- 8) aggregation: gather-only over dst-CSR + self + bias + PReLU ----------------
__global__ void agg_kernel(const float* __restrict__ xw, const float* __restrict__ dis2,
                           const int* __restrict__ rowptr, const int* __restrict__ csrc,
                           const float* __restrict__ ccoef, const float* __restrict__ bias,
                           const float* __restrict__ prelu_a, int layer,
                           float* __restrict__ out) {
    int tid = threadIdx.x;           // 128 -> 8 nodes per block, 16 lanes per node
    int n = blockIdx.x * 8 + (tid >> 4);
    int l = tid & 15;
    int lane = tid & 31;
    unsigned gmask = 0xFFFFu << (lane & 16);

    const float4* __restrict__ xw4 = (const float4*)xw;
    float4 acc = xw4[n * 16 + l];
    float d2 = dis2[n];
    acc.x *= d2; acc.y *= d2; acc.z *= d2; acc.w *= d2;

    int e0 = rowptr[n], e1 = rowptr[n + 1];
    for (int e = e0; e < e1; e += 16) {
        int cnt = e1 - e; if (cnt > 16) cnt = 16;
        int s = 0; float c = 0.0f;
        if (l < cnt) { s = csrc[e + l]; c = ccoef[e + l]; }
        if (cnt == 16) {
            #pragma unroll
            for (int m = 0; m < 16; m++) {
                int   sm = __shfl_sync(gmask, s, m, 16);
                float cm = __shfl_sync(gmask, c, m, 16);
                float4 v = xw4[sm * 16 + l];
                acc.x = fmaf(cm, v.x, acc.x); acc.y = fmaf(cm, v.y, acc.y);
                acc.z = fmaf(cm, v.z, acc.z); acc.w = fmaf(cm, v.w, acc.w);
            }
        } else {
            for (int m = 0; m < cnt; m++) {
                int   sm = __shfl_sync(gmask, s, m, 16);
                float cm = __shfl_sync(gmask, c, m, 16);
                float4 v = xw4[sm * 16 + l];
                acc.x = fmaf(cm, v.x, acc.x); acc.y = fmaf(cm, v.y, acc.y);
                acc.z = fmaf(cm, v.z, acc.z); acc.w = fmaf(cm, v.w, acc.w);
            }
        }
    }
    float4 b4 = ((const float4*)bias)[l];
    acc.x += b4.x; acc.y += b4.y; acc.z += b4.z; acc.w += b4.w;
    float a = prelu_a[layer];
    acc.x = (acc.x >= 0.f) ? acc.x : a * acc.x;
    acc.y = (acc.y >= 0.f) ? acc.y : a * acc.y;
    acc.z = (acc.z >= 0.f) ? acc.z : a * acc.z;
    acc.w = (acc.w >= 0.f) ? acc.w : a * acc.w;
    ((float4*)out)[n * 16 + l] = acc;
}

// ---------------- 9) graph mean pooling ----------------
__global__ void graph_kernel(const float* __restrict__ node_emb, float* __restrict__ gout) {
    int b = blockIdx.x;   // 64
    int d = threadIdx.x;  // 64
    float s = 0.0f;
    #pragma unroll 8
    for (int i = 0; i < NODES_; i++)
        s += node_emb[(b * NODES_ + i) * 64 + d];
    gout[b * 64 + d] = s * (1.0f / (float)NODES_);
}

// ---------------- launch ----------------
extern "C" void kernel_launch(void* const* d_in, const int* in_sizes, int n_in,
                              void* d_out, int out_size) {
    const float* x       = (const float*)d_in[0];
    const int*   ei      = (const int*)d_in[1];
    const float* ea      = (const float*)d_in[2];
    const int*   lengths = (const int*)d_in[3];
    // d_in[4] = batch (unused; batch[n] == n / NODES_)
    const float* W_ih    = (const float*)d_in[5];
    const float* W_hh    = (const float*)d_in[6];
    const float* b_ih    = (const float*)d_in[7];
    const float* b_hh    = (const float*)d_in[8];
    const float* g_w0    = (const float*)d_in[9];
    const float* g_b0    = (const float*)d_in[10];
    const float* g_ws    = (const float*)d_in[11];
    const float* g_bs    = (const float*)d_in[12];
    const float* prelu_a = (const float*)d_in[13];
    float* out = (float*)d_out;

    float *xT, *gruH, *xw, *hbuf, *deg, *dis, *dis2, *ccoef;
    int *cnt, *rowptr, *cursor, *csrc;
    cudaGetSymbolAddress((void**)&xT,     d_xT);
    cudaGetSymbolAddress((void**)&gruH,   d_gruH);
    cudaGetSymbolAddress((void**)&xw,     d_xw);
    cudaGetSymbolAddress((void**)&hbuf,   d_hbuf);
    cudaGetSymbolAddress((void**)&deg,    d_deg);
    cudaGetSymbolAddress((void**)&dis,    d_dis);
    cudaGetSymbolAddress((void**)&dis2,   d_dis2);
    cudaGetSymbolAddress((void**)&cnt,    d_cnt);
    cudaGetSymbolAddress((void**)&rowptr, d_rowptr);
    cudaGetSymbolAddress((void**)&cursor, d_cursor);
    cudaGetSymbolAddress((void**)&csrc,   d_csrc);
    cudaGetSymbolAddress((void**)&ccoef,  d_ccoef);

    // graph preprocessing
    transpose_x_kernel<<<dim3(Nn / 32, Tt / 32), dim3(32, 8)>>>(x, xT);
    init_kernel<<<(Nn + 255) / 256, 256>>>(deg, cnt);
    edge_deg_kernel<<<Ee / 256, 256>>>(ei, ea, deg, cnt);
    scan_kernel<<<1, 1024>>>(cnt, deg, rowptr, cursor, dis, dis2);
    csr_fill_kernel<<<Ee / 256, 256>>>(ei, ea, dis, cursor, csrc, ccoef);

    // GRU
    gru_kernel<<<Nn * 8 / 64, 64>>>(xT, lengths, W_hh, W_ih, b_ih, b_hh, gruH);

    // GCN layers
    gemm_kernel<32><<<Nn / 4, 256>>>(gruH, g_w0, xw);
    agg_kernel<<<Nn / 8, 128>>>(xw, dis2, rowptr, csrc, ccoef, g_b0, prelu_a, 0, hbuf);
    for (int i = 1; i < 4; i++) {
        gemm_kernel<64><<<Nn / 4, 256>>>(hbuf, g_ws + (i - 1) * 64 * 64, xw);
        float* dst = (i == 3) ? out : hbuf;
        agg_kernel<<<Nn / 8, 128>>>(xw, dis2, rowptr, csrc, ccoef,
                                    g_bs + (i - 1) * 64, prelu_a, i, dst);
    }

    // graph embedding appended after node embeddings
    graph_kernel<<<NB, 64>>>(out, out + Nn * 64);
}

// round 2
// speedup vs baseline: 1.4171x; 1.4171x over previous
#include <cuda_runtime.h>
#include <cuda_bf16.h>

// ---------------- problem constants ----------------
constexpr int NB     = 64;     // batches
constexpr int NODES_ = 116;    // nodes per batch
constexpr int Nn     = NB * NODES_;   // 7424
constexpr int Tt     = 256;
constexpr int Hh     = 32;
constexpr int Ee     = Nn * 128;      // 950272
constexpr int HID    = 64;

typedef unsigned long long ull;

// ---------------- device scratch (no cudaMalloc allowed) ----------------
__device__ __align__(16) float d_xT[Tt * Nn];     // transposed x
__device__ __align__(16) float d_gruH[Nn * Hh];   // GRU output
__device__ __align__(16) float d_xw[Nn * HID];    // per-layer h @ W^T
__device__ __align__(16) float d_hbuf[Nn * HID];  // per-layer output
__device__ float d_deg[Nn];
__device__ float d_dis[Nn];
__device__ float d_dis2[Nn];
__device__ __align__(16) int d_cnt[8192];         // padded for int4 scan loads
__device__ int   d_rowptr[Nn + 1];
__device__ int   d_cursor[Nn];
__device__ int   d_csrc[Ee];
__device__ __align__(16) float d_ccoef[Ee];

// ---------------- helpers ----------------
__device__ __forceinline__ float sigm_(float a) {
    return __fdividef(1.0f, 1.0f + __expf(-a));
}
__device__ __forceinline__ float tanh_(float a) {
    return fmaf(-2.0f, __fdividef(1.0f, 1.0f + __expf(2.0f * a)), 1.0f);
}
__device__ __forceinline__ ull fma2_(ull a, ull b, ull c) {
    ull d;
    asm("fma.rn.f32x2 %0, %1, %2, %3;" : "=l"(d) : "l"(a), "l"(b), "l"(c));
    return d;
}
__device__ __forceinline__ ull pack2_(float lo, float hi) {
    ull d;
    asm("mov.b64 %0, {%1, %2};" : "=l"(d) : "f"(lo), "f"(hi));
    return d;
}
__device__ __forceinline__ float hsum2_(ull v) {
    float lo, hi;
    asm("mov.b64 {%0, %1}, %2;" : "=f"(lo), "=f"(hi) : "l"(v));
    return lo + hi;
}

// ---------------- 1) transpose x: [N][T] -> [T][N] ----------------
__global__ void transpose_x_kernel(const float* __restrict__ x, float* __restrict__ xT) {
    __shared__ float tile[32][33];
    int bn = blockIdx.x * 32;
    int bt = blockIdx.y * 32;
    int tx = threadIdx.x, ty = threadIdx.y; // (32, 8)
    #pragma unroll
    for (int j = 0; j < 32; j += 8)
        tile[ty + j][tx] = x[(bn + ty + j) * Tt + (bt + tx)];
    __syncthreads();
    #pragma unroll
    for (int j = 0; j < 32; j += 8)
        xT[(bt + ty + j) * Nn + (bn + tx)] = tile[tx][ty + j];
}

// ---------------- 2) init deg/cnt ----------------
__global__ void init_kernel(float* __restrict__ deg, int* __restrict__ cnt) {
    int i = blockIdx.x * 256 + threadIdx.x;
    if (i < Nn) deg[i] = 1.0f;
    if (i < 8192) cnt[i] = 0;
}

// ---------------- 3) degree + in-count histogram ----------------
__global__ void edge_deg_kernel(const int* __restrict__ ei, const float* __restrict__ ea,
                                float* __restrict__ deg, int* __restrict__ cnt) {
    int e = blockIdx.x * 256 + threadIdx.x;
    if (e >= Ee) return;
    int dst = ei[Ee + e];
    atomicAdd(&deg[dst], ea[e]);
    atomicAdd(&cnt[dst], 1);
}

// ---------------- 4) single-block scan -> rowptr/cursor, plus dis/dis2 ----------------
__global__ void scan_kernel(const int* __restrict__ cnt, const float* __restrict__ deg,
                            int* __restrict__ rowptr, int* __restrict__ cursor,
                            float* __restrict__ dis, float* __restrict__ dis2) {
    __shared__ int ssum[1024];
    int tid = threadIdx.x;
    const int4* c4 = (const int4*)cnt;
    int4 v0 = c4[tid * 2];
    int4 v1 = c4[tid * 2 + 1];
    int vals[8] = {v0.x, v0.y, v0.z, v0.w, v1.x, v1.y, v1.z, v1.w};
    int loc[8];
    int s = 0;
    #pragma unroll
    for (int j = 0; j < 8; j++) { loc[j] = s; s += vals[j]; }
    ssum[tid] = s;
    __syncthreads();
    for (int off = 1; off < 1024; off <<= 1) {
        int add = (tid >= off) ? ssum[tid - off] : 0;
        __syncthreads();
        ssum[tid] += add;
        __syncthreads();
    }
    int pre = (tid > 0) ? ssum[tid - 1] : 0;
    int base = tid * 8;
    #pragma unroll
    for (int j = 0; j < 8; j++) {
        int idx = base + j;
        if (idx < Nn) {
            int v = pre + loc[j];
            rowptr[idx] = v;
            cursor[idx] = v;
        }
    }
    if (tid == 1023) rowptr[Nn] = ssum[1023];
    for (int i = tid; i < Nn; i += 1024) {
        float dg = deg[i];
        float di = rsqrtf(dg);
        dis[i]  = di;
        dis2[i] = di * di;
    }
}

// ---------------- 5) CSR fill (by dst) with precomputed coef ----------------
__global__ void csr_fill_kernel(const int* __restrict__ ei, const float* __restrict__ ea,
                                const float* __restrict__ dis, int* __restrict__ cursor,
                                int* __restrict__ csrc, float* __restrict__ ccoef) {
    int e = blockIdx.x * 256 + threadIdx.x;
    if (e >= Ee) return;
    int src = ei[e];
    int dst = ei[Ee + e];
    float c = dis[src] * ea[e] * dis[dst];
    int pos = atomicAdd(&cursor[dst], 1);
    csrc[pos]  = src;
    ccoef[pos] = c;
}

// ---------------- 6) GRU: 32 threads per node, 1 channel per thread ----------------
// Weights live in registers (packed k-pairs for fma.rn.f32x2); h exchanged via
// broadcast LDS.64 from a per-node shared row. No per-step weight traffic.
__global__ void __launch_bounds__(128) gru_kernel(
    const float* __restrict__ xT, const int* __restrict__ lengths,
    const float* __restrict__ W_hh, const float* __restrict__ W_ih,
    const float* __restrict__ b_ih, const float* __restrict__ b_hh,
    float* __restrict__ out) {
    __shared__ __align__(16) float sh_h[4][32];
    int tid = threadIdx.x;
    int nb = tid >> 5;          // node within block (warp id)
    int j  = tid & 31;          // hidden channel
    int node = blockIdx.x * 4 + nb;
    int len = lengths[node / NODES_];   // uniform across warp

    // one-time weight load into registers: 16 packed k-pairs per gate
    ull wR[16], wZ[16], wN[16];
    #pragma unroll
    for (int p = 0; p < 16; p++) {
        wR[p] = *(const ull*)&W_hh[(j     ) * 32 + 2 * p];
        wZ[p] = *(const ull*)&W_hh[(32 + j) * 32 + 2 * p];
        wN[p] = *(const ull*)&W_hh[(64 + j) * 32 + 2 * p];
    }
    float wiR = W_ih[j], wiZ = W_ih[32 + j], wiN = W_ih[64 + j];
    float bR  = b_ih[j]      + b_hh[j];
    float bZ  = b_ih[32 + j] + b_hh[32 + j];
    float bNx = b_ih[64 + j];
    float bNh = b_hh[64 + j];

    float h = 0.0f;
    sh_h[nb][j] = 0.0f;
    __syncwarp();

    const ull* hp2 = (const ull*)sh_h[nb];
    float xnext = xT[node];
    for (int t = 0; t < len; t++) {
        float xt = xnext;
        xnext = xT[min(t + 1, Tt - 1) * Nn + node];

        ull aR = pack2_(fmaf(xt, wiR, bR), 0.0f);
        ull aZ = pack2_(fmaf(xt, wiZ, bZ), 0.0f);
        ull aN = pack2_(bNh, 0.0f);
        #pragma unroll
        for (int p = 0; p < 16; p++) {
            ull hp = hp2[p];                 // broadcast LDS.64: (h[2p], h[2p+1])
            aR = fma2_(hp, wR[p], aR);
            aZ = fma2_(hp, wZ[p], aZ);
            aN = fma2_(hp, wN[p], aN);
        }
        float r  = sigm_(hsum2_(aR));
        float z  = sigm_(hsum2_(aZ));
        float nn = tanh_(fmaf(xt, wiN, bNx) + r * hsum2_(aN));
        h = fmaf(z, h - nn, nn);             // (1-z)*nn + z*h
        __syncwarp();
        sh_h[nb][j] = h;
        __syncwarp();
    }
    out[node * Hh + j] = h;
}

// ---------------- 7) GEMM: out[n][o] = sum_k in[n][k] * W[o][k] ----------------
template <int Kd>
__global__ void gemm_kernel(const float* __restrict__ in, const float* __restrict__ W,
                            float* __restrict__ out) {
    __shared__ float sW[Kd * 64]; // [k][o]
    __shared__ float sh[4 * Kd];
    int tid = threadIdx.x; // 256
    for (int i = tid; i < Kd * 64; i += 256) {
        int k = i >> 6, o = i & 63;
        sW[i] = W[o * Kd + k];
    }
    int nb = blockIdx.x * 4;
    for (int i = tid; i < 4 * Kd; i += 256)
        sh[i] = in[nb * Kd + i];
    __syncthreads();
    int ln = tid >> 6, o = tid & 63;
    float acc = 0.0f;
    #pragma unroll
    for (int k = 0; k < Kd; k++)
        acc = fmaf(sh[ln * Kd + k], sW[k * 64 + o], acc);
    out[(nb + ln) * 64 + o] = acc;
}

// ---------------- 8) aggregation: gather-only over dst-CSR + self + bias + PReLU ----------------
__global__ void agg_kernel(const float* __restrict__ xw, const float* __restrict__ dis2,
                           const int* __restrict__ rowptr, const int* __restrict__ csrc,
                           const float* __restrict__ ccoef, const float* __restrict__ bias,
                           const float* __restrict__ prelu_a, int layer,
                           float* __restrict__ out) {
    int tid = threadIdx.x;           // 128 -> 8 nodes per block, 16 lanes per node
    int n = blockIdx.x * 8 + (tid >> 4);
    int l = tid & 15;
    int lane = tid & 31;
    unsigned gmask = 0xFFFFu << (lane & 16);

    const float4* __restrict__ xw4 = (const float4*)xw;
    float4 acc = xw4[n * 16 + l];
    float d2 = dis2[n];
    acc.x *= d2; acc.y *= d2; acc.z *= d2; acc.w *= d2;

    int e0 = rowptr[n], e1 = rowptr[n + 1];
    for (int e = e0; e < e1; e += 16) {
        int cnt = e1 - e; if (cnt > 16) cnt = 16;
        int s = 0; float c = 0.0f;
        if (l < cnt) { s = csrc[e + l]; c = ccoef[e + l]; }
        if (cnt == 16) {
            #pragma unroll
            for (int m = 0; m < 16; m++) {
                int   sm = __shfl_sync(gmask, s, m, 16);
                float cm = __shfl_sync(gmask, c, m, 16);
                float4 v = xw4[sm * 16 + l];
                acc.x = fmaf(cm, v.x, acc.x); acc.y = fmaf(cm, v.y, acc.y);
                acc.z = fmaf(cm, v.z, acc.z); acc.w = fmaf(cm, v.w, acc.w);
            }
        } else {
            for (int m = 0; m < cnt; m++) {
                int   sm = __shfl_sync(gmask, s, m, 16);
                float cm = __shfl_sync(gmask, c, m, 16);
                float4 v = xw4[sm * 16 + l];
                acc.x = fmaf(cm, v.x, acc.x); acc.y = fmaf(cm, v.y, acc.y);
                acc.z = fmaf(cm, v.z, acc.z); acc.w = fmaf(cm, v.w, acc.w);
            }
        }
    }
    float4 b4 = ((const float4*)bias)[l];
    acc.x += b4.x; acc.y += b4.y; acc.z += b4.z; acc.w += b4.w;
    float a = prelu_a[layer];
    acc.x = (acc.x >= 0.f) ? acc.x : a * acc.x;
    acc.y = (acc.y >= 0.f) ? acc.y : a * acc.y;
    acc.z = (acc.z >= 0.f) ? acc.z : a * acc.z;
    acc.w = (acc.w >= 0.f) ? acc.w : a * acc.w;
    ((float4*)out)[n * 16 + l] = acc;
}

// ---------------- 9) graph mean pooling ----------------
__global__ void graph_kernel(const float* __restrict__ node_emb, float* __restrict__ gout) {
    int b = blockIdx.x;   // 64
    int d = threadIdx.x;  // 64
    float s = 0.0f;
    #pragma unroll 8
    for (int i = 0; i < NODES_; i++)
        s += node_emb[(b * NODES_ + i) * 64 + d];
    gout[b * 64 + d] = s * (1.0f / (float)NODES_);
}

// ---------------- launch ----------------
extern "C" void kernel_launch(void* const* d_in, const int* in_sizes, int n_in,
                              void* d_out, int out_size) {
    const float* x       = (const float*)d_in[0];
    const int*   ei      = (const int*)d_in[1];
    const float* ea      = (const float*)d_in[2];
    const int*   lengths = (const int*)d_in[3];
    // d_in[4] = batch (unused; batch[n] == n / NODES_)
    const float* W_ih    = (const float*)d_in[5];
    const float* W_hh    = (const float*)d_in[6];
    const float* b_ih    = (const float*)d_in[7];
    const float* b_hh    = (const float*)d_in[8];
    const float* g_w0    = (const float*)d_in[9];
    const float* g_b0    = (const float*)d_in[10];
    const float* g_ws    = (const float*)d_in[11];
    const float* g_bs    = (const float*)d_in[12];
    const float* prelu_a = (const float*)d_in[13];
    float* out = (float*)d_out;

    float *xT, *gruH, *xw, *hbuf, *deg, *dis, *dis2, *ccoef;
    int *cnt, *rowptr, *cursor, *csrc;
    cudaGetSymbolAddress((void**)&xT,     d_xT);
    cudaGetSymbolAddress((void**)&gruH,   d_gruH);
    cudaGetSymbolAddress((void**)&xw,     d_xw);
    cudaGetSymbolAddress((void**)&hbuf,   d_hbuf);
    cudaGetSymbolAddress((void**)&deg,    d_deg);
    cudaGetSymbolAddress((void**)&dis,    d_dis);
    cudaGetSymbolAddress((void**)&dis2,   d_dis2);
    cudaGetSymbolAddress((void**)&cnt,    d_cnt);
    cudaGetSymbolAddress((void**)&rowptr, d_rowptr);
    cudaGetSymbolAddress((void**)&cursor, d_cursor);
    cudaGetSymbolAddress((void**)&csrc,   d_csrc);
    cudaGetSymbolAddress((void**)&ccoef,  d_ccoef);

    // graph preprocessing
    transpose_x_kernel<<<dim3(Nn / 32, Tt / 32), dim3(32, 8)>>>(x, xT);
    init_kernel<<<8192 / 256, 256>>>(deg, cnt);
    edge_deg_kernel<<<Ee / 256, 256>>>(ei, ea, deg, cnt);
    scan_kernel<<<1, 1024>>>(cnt, deg, rowptr, cursor, dis, dis2);
    csr_fill_kernel<<<Ee / 256, 256>>>(ei, ea, dis, cursor, csrc, ccoef);

    // GRU
    gru_kernel<<<Nn / 4, 128>>>(xT, lengths, W_hh, W_ih, b_ih, b_hh, gruH);

    // GCN layers
    gemm_kernel<32><<<Nn / 4, 256>>>(gruH, g_w0, xw);
    agg_kernel<<<Nn / 8, 128>>>(xw, dis2, rowptr, csrc, ccoef, g_b0, prelu_a, 0, hbuf);
    for (int i = 1; i < 4; i++) {
        gemm_kernel<64><<<Nn / 4, 256>>>(hbuf, g_ws + (i - 1) * 64 * 64, xw);
        float* dst = (i == 3) ? out : hbuf;
        agg_kernel<<<Nn / 8, 128>>>(xw, dis2, rowptr, csrc, ccoef,
                                    g_bs + (i - 1) * 64, prelu_a, i, dst);
    }

    // graph embedding appended after node embeddings
    graph_kernel<<<NB, 64>>>(out, out + Nn * 64);
}

// round 3
// speedup vs baseline: 1.4805x; 1.0447x over previous
#include <cuda_runtime.h>
#include <cuda_fp16.h>
#include <cuda_bf16.h>

// ---------------- problem constants ----------------
constexpr int NB     = 64;     // batches
constexpr int NODES_ = 116;    // nodes per batch
constexpr int Nn     = NB * NODES_;   // 7424
constexpr int Tt     = 256;
constexpr int Hh     = 32;
constexpr int Ee     = Nn * 128;      // 950272
constexpr int HID    = 64;

typedef unsigned long long ull;

// ---------------- device scratch (no cudaMalloc allowed) ----------------
__device__ __align__(16) float d_xT[Tt * Nn];     // transposed x
__device__ __align__(16) float d_gruH[Nn * Hh];   // GRU output
__device__ __align__(16) float d_xw[Nn * HID];    // per-layer h @ W^T (fp32, self term)
__device__ __align__(16) __half d_xwh[Nn * HID];  // fp16 copy for gathers
__device__ __align__(16) float d_hbuf[Nn * HID];  // per-layer output
__device__ float d_deg[Nn];
__device__ float d_dis[Nn];
__device__ float d_dis2[Nn];
__device__ __align__(16) int d_cnt[8192];         // padded for int4 scan loads
__device__ int   d_rowptr[Nn + 1];
__device__ int   d_cursor[Nn];
__device__ __align__(16) ull d_edge[Ee];          // packed (src:int lo32, coef:f32 hi32)

// ---------------- helpers ----------------
__device__ __forceinline__ float sigm_(float a) {
    return __fdividef(1.0f, 1.0f + __expf(-a));
}
__device__ __forceinline__ float tanh_(float a) {
    return fmaf(-2.0f, __fdividef(1.0f, 1.0f + __expf(2.0f * a)), 1.0f);
}
__device__ __forceinline__ ull fma2_(ull a, ull b, ull c) {
    ull d;
    asm("fma.rn.f32x2 %0, %1, %2, %3;" : "=l"(d) : "l"(a), "l"(b), "l"(c));
    return d;
}
__device__ __forceinline__ ull pack2_(float lo, float hi) {
    ull d;
    asm("mov.b64 %0, {%1, %2};" : "=l"(d) : "f"(lo), "f"(hi));
    return d;
}
__device__ __forceinline__ float hsum2_(ull v) {
    float lo, hi;
    asm("mov.b64 {%0, %1}, %2;" : "=f"(lo), "=f"(hi) : "l"(v));
    return lo + hi;
}

// ---------------- 1) transpose x: [N][T] -> [T][N] ----------------
__global__ void transpose_x_kernel(const float* __restrict__ x, float* __restrict__ xT) {
    __shared__ float tile[32][33];
    int bn = blockIdx.x * 32;
    int bt = blockIdx.y * 32;
    int tx = threadIdx.x, ty = threadIdx.y; // (32, 8)
    #pragma unroll
    for (int j = 0; j < 32; j += 8)
        tile[ty + j][tx] = x[(bn + ty + j) * Tt + (bt + tx)];
    __syncthreads();
    #pragma unroll
    for (int j = 0; j < 32; j += 8)
        xT[(bt + ty + j) * Nn + (bn + tx)] = tile[tx][ty + j];
}

// ---------------- 2) init deg/cnt ----------------
__global__ void init_kernel(float* __restrict__ deg, int* __restrict__ cnt) {
    int i = blockIdx.x * 256 + threadIdx.x;
    if (i < Nn) deg[i] = 1.0f;
    if (i < 8192) cnt[i] = 0;
}

// ---------------- 3) degree + in-count histogram ----------------
__global__ void edge_deg_kernel(const int* __restrict__ ei, const float* __restrict__ ea,
                                float* __restrict__ deg, int* __restrict__ cnt) {
    int e = blockIdx.x * 256 + threadIdx.x;
    if (e >= Ee) return;
    int dst = ei[Ee + e];
    atomicAdd(&deg[dst], ea[e]);
    atomicAdd(&cnt[dst], 1);
}

// ---------------- 4) single-block scan -> rowptr/cursor, plus dis/dis2 ----------------
__global__ void scan_kernel(const int* __restrict__ cnt, const float* __restrict__ deg,
                            int* __restrict__ rowptr, int* __restrict__ cursor,
                            float* __restrict__ dis, float* __restrict__ dis2) {
    __shared__ int ssum[1024];
    int tid = threadIdx.x;
    const int4* c4 = (const int4*)cnt;
    int4 v0 = c4[tid * 2];
    int4 v1 = c4[tid * 2 + 1];
    int vals[8] = {v0.x, v0.y, v0.z, v0.w, v1.x, v1.y, v1.z, v1.w};
    int loc[8];
    int s = 0;
    #pragma unroll
    for (int j = 0; j < 8; j++) { loc[j] = s; s += vals[j]; }
    ssum[tid] = s;
    __syncthreads();
    for (int off = 1; off < 1024; off <<= 1) {
        int add = (tid >= off) ? ssum[tid - off] : 0;
        __syncthreads();
        ssum[tid] += add;
        __syncthreads();
    }
    int pre = (tid > 0) ? ssum[tid - 1] : 0;
    int base = tid * 8;
    #pragma unroll
    for (int j = 0; j < 8; j++) {
        int idx = base + j;
        if (idx < Nn) {
            int v = pre + loc[j];
            rowptr[idx] = v;
            cursor[idx] = v;
        }
    }
    if (tid == 1023) rowptr[Nn] = ssum[1023];
    for (int i = tid; i < Nn; i += 1024) {
        float dg = deg[i];
        float di = rsqrtf(dg);
        dis[i]  = di;
        dis2[i] = di * di;
    }
}

// ---------------- 5) CSR fill (by dst), packed (src, coef) records ----------------
__global__ void csr_fill_kernel(const int* __restrict__ ei, const float* __restrict__ ea,
                                const float* __restrict__ dis, int* __restrict__ cursor,
                                ull* __restrict__ edge) {
    int e = blockIdx.x * 256 + threadIdx.x;
    if (e >= Ee) return;
    int src = ei[e];
    int dst = ei[Ee + e];
    float c = dis[src] * ea[e] * dis[dst];
    int pos = atomicAdd(&cursor[dst], 1);
    edge[pos] = ((ull)__float_as_uint(c) << 32) | (unsigned)src;
}

// ---------------- 6) GRU: 32 threads per node, 1 channel per thread ----------------
// Register-resident packed weights; h exchanged via double-buffered shared row
// (LDS.128 broadcast, single syncwarp per step).
__global__ void __launch_bounds__(128) gru_kernel(
    const float* __restrict__ xT, const int* __restrict__ lengths,
    const float* __restrict__ W_hh, const float* __restrict__ W_ih,
    const float* __restrict__ b_ih, const float* __restrict__ b_hh,
    float* __restrict__ out) {
    __shared__ __align__(16) float sh_h[2][4][32];
    int tid = threadIdx.x;
    int nb = tid >> 5;          // node within block (warp id)
    int j  = tid & 31;          // hidden channel
    int node = blockIdx.x * 4 + nb;
    int len = lengths[node / NODES_];   // uniform across warp

    // one-time weight load into registers: 16 packed k-pairs per gate
    ull wR[16], wZ[16], wN[16];
    #pragma unroll
    for (int p = 0; p < 16; p++) {
        wR[p] = *(const ull*)&W_hh[(j     ) * 32 + 2 * p];
        wZ[p] = *(const ull*)&W_hh[(32 + j) * 32 + 2 * p];
        wN[p] = *(const ull*)&W_hh[(64 + j) * 32 + 2 * p];
    }
    float wiR = W_ih[j], wiZ = W_ih[32 + j], wiN = W_ih[64 + j];
    float bR  = b_ih[j]      + b_hh[j];
    float bZ  = b_ih[32 + j] + b_hh[32 + j];
    float bNx = b_ih[64 + j];
    float bNh = b_hh[64 + j];

    float h = 0.0f;
    sh_h[0][nb][j] = 0.0f;
    __syncwarp();

    int buf = 0;
    float xnext = xT[node];
    for (int t = 0; t < len; t++) {
        float xt = xnext;
        xnext = xT[min(t + 1, Tt - 1) * Nn + node];

        ull aR = pack2_(fmaf(xt, wiR, bR), 0.0f);
        ull aZ = pack2_(fmaf(xt, wiZ, bZ), 0.0f);
        ull aN = pack2_(bNh, 0.0f);
        const longlong2* hp = (const longlong2*)sh_h[buf][nb];
        #pragma unroll
        for (int p = 0; p < 8; p++) {
            longlong2 hv = hp[p];            // broadcast LDS.128: 4 h values
            ull h0 = (ull)hv.x, h1 = (ull)hv.y;
            aR = fma2_(h0, wR[2 * p], aR);
            aZ = fma2_(h0, wZ[2 * p], aZ);
            aN = fma2_(h0, wN[2 * p], aN);
            aR = fma2_(h1, wR[2 * p + 1], aR);
            aZ = fma2_(h1, wZ[2 * p + 1], aZ);
            aN = fma2_(h1, wN[2 * p + 1], aN);
        }
        float r  = sigm_(hsum2_(aR));
        float z  = sigm_(hsum2_(aZ));
        float nn = tanh_(fmaf(xt, wiN, bNx) + r * hsum2_(aN));
        h = fmaf(z, h - nn, nn);             // (1-z)*nn + z*h
        sh_h[buf ^ 1][nb][j] = h;
        __syncwarp();
        buf ^= 1;
    }
    out[node * Hh + j] = h;
}

// ---------------- 7) GEMM: out[n][o] = sum_k in[n][k] * W[o][k]; also fp16 copy ----------------
template <int Kd>
__global__ void gemm_kernel(const float* __restrict__ in, const float* __restrict__ W,
                            float* __restrict__ out, __half* __restrict__ outh) {
    __shared__ float sW[Kd * 64]; // [k][o]
    __shared__ float sh[4 * Kd];
    int tid = threadIdx.x; // 256
    for (int i = tid; i < Kd * 64; i += 256) {
        int k = i >> 6, o = i & 63;
        sW[i] = W[o * Kd + k];
    }
    int nb = blockIdx.x * 4;
    for (int i = tid; i < 4 * Kd; i += 256)
        sh[i] = in[nb * Kd + i];
    __syncthreads();
    int ln = tid >> 6, o = tid & 63;
    float acc = 0.0f;
    #pragma unroll
    for (int k = 0; k < Kd; k++)
        acc = fmaf(sh[ln * Kd + k], sW[k * 64 + o], acc);
    out[(nb + ln) * 64 + o]  = acc;
    outh[(nb + ln) * 64 + o] = __float2half(acc);
}

// ---------------- 8) aggregation: fp16 gather over dst-CSR + fp32 self + bias + PReLU ----------------
__global__ void agg_kernel(const float* __restrict__ xw, const __half* __restrict__ xwh,
                           const float* __restrict__ dis2,
                           const int* __restrict__ rowptr, const ull* __restrict__ edge,
                           const float* __restrict__ bias,
                           const float* __restrict__ prelu_a, int layer,
                           float* __restrict__ out) {
    int tid = threadIdx.x;           // 128 -> 8 nodes per block, 16 lanes per node
    int n = blockIdx.x * 8 + (tid >> 4);
    int l = tid & 15;
    int lane = tid & 31;
    unsigned gmask = 0xFFFFu << (lane & 16);

    const float4* __restrict__ xw4 = (const float4*)xw;
    const uint2* __restrict__ xh = (const uint2*)xwh;   // 4 halves per element
    float4 acc = xw4[n * 16 + l];
    float d2 = dis2[n];
    acc.x *= d2; acc.y *= d2; acc.z *= d2; acc.w *= d2;

    int e0 = rowptr[n], e1 = rowptr[n + 1];
    for (int e = e0; e < e1; e += 16) {
        ull rec = 0;                              // zero coef pads partial chunks
        if (e + l < e1) rec = edge[e + l];
        #pragma unroll
        for (int m = 0; m < 16; m++) {
            ull rm = __shfl_sync(gmask, rec, m, 16);
            int   sm = (int)(unsigned)rm;
            float cm = __uint_as_float((unsigned)(rm >> 32));
            uint2 hv = xh[sm * 16 + l];
            float2 f0 = __half22float2(*(__half2*)&hv.x);
            float2 f1 = __half22float2(*(__half2*)&hv.y);
            acc.x = fmaf(cm, f0.x, acc.x); acc.y = fmaf(cm, f0.y, acc.y);
            acc.z = fmaf(cm, f1.x, acc.z); acc.w = fmaf(cm, f1.y, acc.w);
        }
    }
    float4 b4 = ((const float4*)bias)[l];
    acc.x += b4.x; acc.y += b4.y; acc.z += b4.z; acc.w += b4.w;
    float a = prelu_a[layer];
    acc.x = (acc.x >= 0.f) ? acc.x : a * acc.x;
    acc.y = (acc.y >= 0.f) ? acc.y : a * acc.y;
    acc.z = (acc.z >= 0.f) ? acc.z : a * acc.z;
    acc.w = (acc.w >= 0.f) ? acc.w : a * acc.w;
    ((float4*)out)[n * 16 + l] = acc;
}

// ---------------- 9) graph mean pooling ----------------
__global__ void graph_kernel(const float* __restrict__ node_emb, float* __restrict__ gout) {
    int b = blockIdx.x;   // 64
    int d = threadIdx.x;  // 64
    float s = 0.0f;
    #pragma unroll 8
    for (int i = 0; i < NODES_; i++)
        s += node_emb[(b * NODES_ + i) * 64 + d];
    gout[b * 64 + d] = s * (1.0f / (float)NODES_);
}

// ---------------- launch ----------------
extern "C" void kernel_launch(void* const* d_in, const int* in_sizes, int n_in,
                              void* d_out, int out_size) {
    const float* x       = (const float*)d_in[0];
    const int*   ei      = (const int*)d_in[1];
    const float* ea      = (const float*)d_in[2];
    const int*   lengths = (const int*)d_in[3];
    // d_in[4] = batch (unused; batch[n] == n / NODES_)
    const float* W_ih    = (const float*)d_in[5];
    const float* W_hh    = (const float*)d_in[6];
    const float* b_ih    = (const float*)d_in[7];
    const float* b_hh    = (const float*)d_in[8];
    const float* g_w0    = (const float*)d_in[9];
    const float* g_b0    = (const float*)d_in[10];
    const float* g_ws    = (const float*)d_in[11];
    const float* g_bs    = (const float*)d_in[12];
    const float* prelu_a = (const float*)d_in[13];
    float* out = (float*)d_out;

    float *xT, *gruH, *xw, *hbuf, *deg, *dis, *dis2;
    __half* xwh;
    int *cnt, *rowptr, *cursor;
    ull* edge;
    cudaGetSymbolAddress((void**)&xT,     d_xT);
    cudaGetSymbolAddress((void**)&gruH,   d_gruH);
    cudaGetSymbolAddress((void**)&xw,     d_xw);
    cudaGetSymbolAddress((void**)&xwh,    d_xwh);
    cudaGetSymbolAddress((void**)&hbuf,   d_hbuf);
    cudaGetSymbolAddress((void**)&deg,    d_deg);
    cudaGetSymbolAddress((void**)&dis,    d_dis);
    cudaGetSymbolAddress((void**)&dis2,   d_dis2);
    cudaGetSymbolAddress((void**)&cnt,    d_cnt);
    cudaGetSymbolAddress((void**)&rowptr, d_rowptr);
    cudaGetSymbolAddress((void**)&cursor, d_cursor);
    cudaGetSymbolAddress((void**)&edge,   d_edge);

    // graph preprocessing
    transpose_x_kernel<<<dim3(Nn / 32, Tt / 32), dim3(32, 8)>>>(x, xT);
    init_kernel<<<8192 / 256, 256>>>(deg, cnt);
    edge_deg_kernel<<<Ee / 256, 256>>>(ei, ea, deg, cnt);
    scan_kernel<<<1, 1024>>>(cnt, deg, rowptr, cursor, dis, dis2);
    csr_fill_kernel<<<Ee / 256, 256>>>(ei, ea, dis, cursor, edge);

    // GRU
    gru_kernel<<<Nn / 4, 128>>>(xT, lengths, W_hh, W_ih, b_ih, b_hh, gruH);

    // GCN layers
    gemm_kernel<32><<<Nn / 4, 256>>>(gruH, g_w0, xw, xwh);
    agg_kernel<<<Nn / 8, 128>>>(xw, xwh, dis2, rowptr, edge, g_b0, prelu_a, 0, hbuf);
    for (int i = 1; i < 4; i++) {
        gemm_kernel<64><<<Nn / 4, 256>>>(hbuf, g_ws + (i - 1) * 64 * 64, xw, xwh);
        float* dst = (i == 3) ? out : hbuf;
        agg_kernel<<<Nn / 8, 128>>>(xw, xwh, dis2, rowptr, edge,
                                    g_bs + (i - 1) * 64, prelu_a, i, dst);
    }

    // graph embedding appended after node embeddings
    graph_kernel<<<NB, 64>>>(out, out + Nn * 64);
}

// round 5
// speedup vs baseline: 1.5904x; 1.0743x over previous
#include <cuda_runtime.h>
#include <cuda_fp16.h>
#include <cuda_bf16.h>

// ---------------- problem constants ----------------
constexpr int NB     = 64;     // batches
constexpr int NODES_ = 116;    // nodes per batch
constexpr int Nn     = NB * NODES_;   // 7424
constexpr int Tt     = 256;
constexpr int Hh     = 32;
constexpr int Ee     = Nn * 128;      // 950272
constexpr int HID    = 64;
constexpr int BPB    = NODES_ / 4;    // GRU blocks per batch = 29

typedef unsigned long long ull;

// ---------------- device scratch (no cudaMalloc allowed) ----------------
__device__ __align__(16) float d_xT[(Tt + 1) * Nn]; // transposed x (+1 pad row)
__device__ __align__(16) float d_gruH[Nn * Hh];   // GRU output
__device__ __align__(16) float d_xw[Nn * HID];    // per-layer h @ W^T (fp32, self term)
__device__ __align__(16) __half d_xwh[Nn * HID];  // fp16 copy for gathers
__device__ __align__(16) float d_hbuf[Nn * HID];  // per-layer output
__device__ float d_deg[Nn];
__device__ float d_dis[Nn];
__device__ float d_dis2[Nn];
__device__ __align__(16) int d_cnt[8192];         // padded for int4 scan loads
__device__ int   d_rowptr[Nn + 1];
__device__ int   d_cursor[Nn];
__device__ int   d_order[NB];                     // batches sorted by length desc
__device__ __align__(16) ull d_edge[Ee];          // packed (src:int lo32, coef:f32 hi32)

// ---------------- helpers ----------------
__device__ __forceinline__ float sigm_(float a) {
    return __fdividef(1.0f, 1.0f + __expf(-a));
}
__device__ __forceinline__ float tanh_(float a) {
    return fmaf(-2.0f, __fdividef(1.0f, 1.0f + __expf(2.0f * a)), 1.0f);
}
__device__ __forceinline__ ull fma2_(ull a, ull b, ull c) {
    ull d;
    asm("fma.rn.f32x2 %0, %1, %2, %3;" : "=l"(d) : "l"(a), "l"(b), "l"(c));
    return d;
}
__device__ __forceinline__ ull pack2_(float lo, float hi) {
    ull d;
    asm("mov.b64 %0, {%1, %2};" : "=l"(d) : "f"(lo), "f"(hi));
    return d;
}
__device__ __forceinline__ float hsum2_(ull v) {
    float lo, hi;
    asm("mov.b64 {%0, %1}, %2;" : "=f"(lo), "=f"(hi) : "l"(v));
    return lo + hi;
}

// ---------------- 1) transpose x [N][T]->[T][N]  (+ fused deg/cnt init) ----------------
__global__ void transpose_x_kernel(const float* __restrict__ x, float* __restrict__ xT,
                                   float* __restrict__ deg, int* __restrict__ cnt) {
    __shared__ float tile[32][33];
    int bn = blockIdx.x * 32;
    int bt = blockIdx.y * 32;
    int tx = threadIdx.x, ty = threadIdx.y; // (32, 8)
    #pragma unroll
    for (int j = 0; j < 32; j += 8)
        tile[ty + j][tx] = x[(bn + ty + j) * Tt + (bt + tx)];
    __syncthreads();
    #pragma unroll
    for (int j = 0; j < 32; j += 8)
        xT[(bt + ty + j) * Nn + (bn + tx)] = tile[tx][ty + j];
    // fused init: 1856 blocks x 256 threads covers 8192 slots
    int gid = (blockIdx.y * gridDim.x + blockIdx.x) * 256 + ty * 32 + tx;
    if (gid < 8192) {
        cnt[gid] = 0;
        if (gid < Nn) deg[gid] = 1.0f;
    }
}

// ---------------- 2) degree + in-count histogram ----------------
__global__ void edge_deg_kernel(const int* __restrict__ ei, const float* __restrict__ ea,
                                float* __restrict__ deg, int* __restrict__ cnt) {
    int e = blockIdx.x * 256 + threadIdx.x;
    if (e >= Ee) return;
    int dst = ei[Ee + e];
    atomicAdd(&deg[dst], ea[e]);
    atomicAdd(&cnt[dst], 1);
}

// ---------------- 3) sort batches by length (descending) for LPT scheduling ----------------
__global__ void sort_kernel(const int* __restrict__ lengths, int* __restrict__ order) {
    __shared__ int sl[NB];
    int l = threadIdx.x;     // 64
    int v = lengths[l];
    sl[l] = v;
    __syncthreads();
    int r = 0;
    #pragma unroll
    for (int m = 0; m < NB; m++) {
        int vm = sl[m];
        r += (vm > v) || (vm == v && m < l);
    }
    order[r] = l;
}

// ---------------- 4) GRU: 32 threads per node, 1 channel per thread ----------------
// Register-resident packed weights; h exchanged via double-buffered shared row
// (LDS.128 broadcast, single syncwarp per step). LPT batch order via d_order.
__global__ void __launch_bounds__(128) gru_kernel(
    const float* __restrict__ xT, const int* __restrict__ lengths,
    const int* __restrict__ order,
    const float* __restrict__ W_hh, const float* __restrict__ W_ih,
    const float* __restrict__ b_ih, const float* __restrict__ b_hh,
    float* __restrict__ out) {
    __shared__ __align__(16) float sh_h[2][4][32];
    int tid = threadIdx.x;
    int nb = tid >> 5;          // node within block (warp id)
    int j  = tid & 31;          // hidden channel
    int batch = order[blockIdx.x / BPB];
    int node = batch * NODES_ + (blockIdx.x % BPB) * 4 + nb;
    int len = lengths[batch];   // uniform across warp

    // one-time weight load into registers: 16 packed k-pairs per gate
    ull wR[16], wZ[16], wN[16];
    #pragma unroll
    for (int p = 0; p < 16; p++) {
        wR[p] = *(const ull*)&W_hh[(j     ) * 32 + 2 * p];
        wZ[p] = *(const ull*)&W_hh[(32 + j) * 32 + 2 * p];
        wN[p] = *(const ull*)&W_hh[(64 + j) * 32 + 2 * p];
    }
    float wiR = W_ih[j], wiZ = W_ih[32 + j], wiN = W_ih[64 + j];
    float bR  = b_ih[j]      + b_hh[j];
    float bZ  = b_ih[32 + j] + b_hh[32 + j];
    float bNx = b_ih[64 + j];
    float bNh = b_hh[64 + j];

    float h = 0.0f;
    sh_h[0][nb][j] = 0.0f;
    __syncwarp();

    const longlong2* hrd = (const longlong2*)sh_h[0][nb];
    float*           hwr = sh_h[1][nb];
    const float* xp = xT + node;
    float xnext = *xp;
    xp += Nn;
    for (int t = 0; t < len; t++) {
        float xt = xnext;
        xnext = *xp;          // row t+1 (padded row Tt for final iter)
        xp += Nn;

        ull aR = pack2_(fmaf(xt, wiR, bR), 0.0f);
        ull aZ = pack2_(fmaf(xt, wiZ, bZ), 0.0f);
        ull aN = pack2_(bNh, 0.0f);
        #pragma unroll
        for (int p = 0; p < 8; p++) {
            longlong2 hv = hrd[p];           // broadcast LDS.128: 4 h values
            ull h0 = (ull)hv.x, h1 = (ull)hv.y;
            aR = fma2_(h0, wR[2 * p], aR);
            aZ = fma2_(h0, wZ[2 * p], aZ);
            aN = fma2_(h0, wN[2 * p], aN);
            aR = fma2_(h1, wR[2 * p + 1], aR);
            aZ = fma2_(h1, wZ[2 * p + 1], aZ);
            aN = fma2_(h1, wN[2 * p + 1], aN);
        }
        float r  = sigm_(hsum2_(aR));
        float z  = sigm_(hsum2_(aZ));
        float nn = tanh_(fmaf(xt, wiN, bNx) + r * hsum2_(aN));
        h = fmaf(z, h - nn, nn);             // (1-z)*nn + z*h
        hwr[j] = h;
        __syncwarp();
        // swap read/write buffers
        float* tmp = (float*)hrd;
        hrd = (const longlong2*)hwr;
        hwr = tmp;
    }
    out[node * Hh + j] = h;
}

// ---------------- 5) scan: warp-shuffle two-level -> rowptr/cursor + dis/dis2 ----------------
__global__ void scan_kernel(const int* __restrict__ cnt, const float* __restrict__ deg,
                            int* __restrict__ rowptr, int* __restrict__ cursor,
                            float* __restrict__ dis, float* __restrict__ dis2) {
    __shared__ int swarp[32];
    int tid = threadIdx.x;          // 1024
    int wid = tid >> 5, lane = tid & 31;
    const int4* c4 = (const int4*)cnt;
    int4 v0 = c4[tid * 2];
    int4 v1 = c4[tid * 2 + 1];
    int vals[8] = {v0.x, v0.y, v0.z, v0.w, v1.x, v1.y, v1.z, v1.w};
    int loc[8];
    int s = 0;
    #pragma unroll
    for (int j = 0; j < 8; j++) { loc[j] = s; s += vals[j]; }
    // inclusive warp scan of s
    int sc = s;
    #pragma unroll
    for (int off = 1; off < 32; off <<= 1) {
        int n = __shfl_up_sync(0xffffffffu, sc, off);
        if (lane >= off) sc += n;
    }
    if (lane == 31) swarp[wid] = sc;
    __syncthreads();
    if (wid == 0) {
        int w = swarp[lane];
        #pragma unroll
        for (int off = 1; off < 32; off <<= 1) {
            int n = __shfl_up_sync(0xffffffffu, w, off);
            if (lane >= off) w += n;
        }
        swarp[lane] = w;
    }
    __syncthreads();
    int base = (wid > 0 ? swarp[wid - 1] : 0) + (sc - s);  // exclusive prefix
    int idx0 = tid * 8;
    #pragma unroll
    for (int j = 0; j < 8; j++) {
        int idx = idx0 + j;
        if (idx < Nn) {
            int v = base + loc[j];
            rowptr[idx] = v;
            cursor[idx] = v;
        }
    }
    if (tid == 1023) rowptr[Nn] = base + s;
    for (int i = tid; i < Nn; i += 1024) {
        float dg = deg[i];
        float di = rsqrtf(dg);
        dis[i]  = di;
        dis2[i] = di * di;
    }
}

// ---------------- 6) CSR fill (by dst), packed (src, coef) records ----------------
__global__ void csr_fill_kernel(const int* __restrict__ ei, const float* __restrict__ ea,
                                const float* __restrict__ dis, int* __restrict__ cursor,
                                ull* __restrict__ edge) {
    int e = blockIdx.x * 256 + threadIdx.x;
    if (e >= Ee) return;
    int src = ei[e];
    int dst = ei[Ee + e];
    float c = dis[src] * ea[e] * dis[dst];
    int pos = atomicAdd(&cursor[dst], 1);
    edge[pos] = ((ull)__float_as_uint(c) << 32) | (unsigned)src;
}

// ---------------- 7) GEMM: out[n][o] = sum_k in[n][k] * W[o][k]; also fp16 copy ----------------
template <int Kd>
__global__ void gemm_kernel(const float* __restrict__ in, const float* __restrict__ W,
                            float* __restrict__ out, __half* __restrict__ outh) {
    __shared__ float sW[Kd * 64]; // [k][o]
    __shared__ float sh[4 * Kd];
    int tid = threadIdx.x; // 256
    for (int i = tid; i < Kd * 64; i += 256) {
        int k = i >> 6, o = i & 63;
        sW[i] = W[o * Kd + k];
    }
    int nb = blockIdx.x * 4;
    for (int i = tid; i < 4 * Kd; i += 256)
        sh[i] = in[nb * Kd + i];
    __syncthreads();
    int ln = tid >> 6, o = tid & 63;
    float acc = 0.0f;
    #pragma unroll
    for (int k = 0; k < Kd; k++)
        acc = fmaf(sh[ln * Kd + k], sW[k * 64 + o], acc);
    out[(nb + ln) * 64 + o]  = acc;
    outh[(nb + ln) * 64 + o] = __float2half(acc);
}

// ---------------- 8) aggregation: fp16 gather over dst-CSR + fp32 self + bias + PReLU ----------------
__global__ void agg_kernel(const float* __restrict__ xw, const __half* __restrict__ xwh,
                           const float* __restrict__ dis2,
                           const int* __restrict__ rowptr, const ull* __restrict__ edge,
                           const float* __restrict__ bias,
                           const float* __restrict__ prelu_a, int layer,
                           float* __restrict__ out) {
    int tid = threadIdx.x;           // 128 -> 8 nodes per block, 16 lanes per node
    int n = blockIdx.x * 8 + (tid >> 4);
    int l = tid & 15;
    int lane = tid & 31;
    unsigned gmask = 0xFFFFu << (lane & 16);

    const float4* __restrict__ xw4 = (const float4*)xw;
    const uint2* __restrict__ xh = (const uint2*)xwh;   // 4 halves per element
    float4 acc = xw4[n * 16 + l];
    float d2 = dis2[n];
    acc.x *= d2; acc.y *= d2; acc.z *= d2; acc.w *= d2;

    int e0 = rowptr[n], e1 = rowptr[n + 1];
    for (int e = e0; e < e1; e += 16) {
        ull rec = 0;                              // zero coef pads partial chunks
        if (e + l < e1) rec = edge[e + l];
        #pragma unroll
        for (int m = 0; m < 16; m++) {
            ull rm = __shfl_sync(gmask, rec, m, 16);
            int   sm = (int)(unsigned)rm;
            float cm = __uint_as_float((unsigned)(rm >> 32));
            uint2 hv = xh[sm * 16 + l];
            float2 f0 = __half22float2(*(__half2*)&hv.x);
            float2 f1 = __half22float2(*(__half2*)&hv.y);
            acc.x = fmaf(cm, f0.x, acc.x); acc.y = fmaf(cm, f0.y, acc.y);
            acc.z = fmaf(cm, f1.x, acc.z); acc.w = fmaf(cm, f1.y, acc.w);
        }
    }
    float4 b4 = ((const float4*)bias)[l];
    acc.x += b4.x; acc.y += b4.y; acc.z += b4.z; acc.w += b4.w;
    float a = prelu_a[layer];
    acc.x = (acc.x >= 0.f) ? acc.x : a * acc.x;
    acc.y = (acc.y >= 0.f) ? acc.y : a * acc.y;
    acc.z = (acc.z >= 0.f) ? acc.z : a * acc.z;
    acc.w = (acc.w >= 0.f) ? acc.w : a * acc.w;
    ((float4*)out)[n * 16 + l] = acc;
}

// ---------------- 9) graph mean pooling ----------------
__global__ void graph_kernel(const float* __restrict__ node_emb, float* __restrict__ gout) {
    int b = blockIdx.x;   // 64
    int d = threadIdx.x;  // 64
    float s = 0.0f;
    #pragma unroll 8
    for (int i = 0; i < NODES_; i++)
        s += node_emb[(b * NODES_ + i) * 64 + d];
    gout[b * 64 + d] = s * (1.0f / (float)NODES_);
}

// ---------------- launch ----------------
extern "C" void kernel_launch(void* const* d_in, const int* in_sizes, int n_in,
                              void* d_out, int out_size) {
    const float* x       = (const float*)d_in[0];
    const int*   ei      = (const int*)d_in[1];
    const float* ea      = (const float*)d_in[2];
    const int*   lengths = (const int*)d_in[3];
    // d_in[4] = batch (unused; batch[n] == n / NODES_)
    const float* W_ih    = (const float*)d_in[5];
    const float* W_hh    = (const float*)d_in[6];
    const float* b_ih    = (const float*)d_in[7];
    const float* b_hh    = (const float*)d_in[8];
    const float* g_w0    = (const float*)d_in[9];
    const float* g_b0    = (const float*)d_in[10];
    const float* g_ws    = (const float*)d_in[11];
    const float* g_bs    = (const float*)d_in[12];
    const float* prelu_a = (const float*)d_in[13];
    float* out = (float*)d_out;

    float *xT, *gruH, *xw, *hbuf, *deg, *dis, *dis2;
    __half* xwh;
    int *cnt, *rowptr, *cursor, *order;
    ull* edge;
    cudaGetSymbolAddress((void**)&xT,     d_xT);
    cudaGetSymbolAddress((void**)&gruH,   d_gruH);
    cudaGetSymbolAddress((void**)&xw,     d_xw);
    cudaGetSymbolAddress((void**)&xwh,    d_xwh);
    cudaGetSymbolAddress((void**)&hbuf,   d_hbuf);
    cudaGetSymbolAddress((void**)&deg,    d_deg);
    cudaGetSymbolAddress((void**)&dis,    d_dis);
    cudaGetSymbolAddress((void**)&dis2,   d_dis2);
    cudaGetSymbolAddress((void**)&cnt,    d_cnt);
    cudaGetSymbolAddress((void**)&rowptr, d_rowptr);
    cudaGetSymbolAddress((void**)&cursor, d_cursor);
    cudaGetSymbolAddress((void**)&order,  d_order);
    cudaGetSymbolAddress((void**)&edge,   d_edge);

    // 1: transpose (+deg/cnt init)
    transpose_x_kernel<<<dim3(Nn / 32, Tt / 32), dim3(32, 8)>>>(x, xT, deg, cnt);
    // 2: degree + count histogram
    edge_deg_kernel<<<Ee / 256, 256>>>(ei, ea, deg, cnt);
    // 3: LPT batch order
    sort_kernel<<<1, NB>>>(lengths, order);
    // 4: GRU  (profiled slot)
    gru_kernel<<<Nn / 4, 128>>>(xT, lengths, order, W_hh, W_ih, b_ih, b_hh, gruH);
    // 5: scan
    scan_kernel<<<1, 1024>>>(cnt, deg, rowptr, cursor, dis, dis2);
    // 6: CSR fill
    csr_fill_kernel<<<Ee / 256, 256>>>(ei, ea, dis, cursor, edge);

    // GCN layers
    gemm_kernel<32><<<Nn / 4, 256>>>(gruH, g_w0, xw, xwh);
    agg_kernel<<<Nn / 8, 128>>>(xw, xwh, dis2, rowptr, edge, g_b0, prelu_a, 0, hbuf);
    for (int i = 1; i < 4; i++) {
        gemm_kernel<64><<<Nn / 4, 256>>>(hbuf, g_ws + (i - 1) * 64 * 64, xw, xwh);
        float* dst = (i == 3) ? out : hbuf;
        agg_kernel<<<Nn / 8, 128>>>(xw, xwh, dis2, rowptr, edge,
                                    g_bs + (i - 1) * 64, prelu_a, i, dst);
    }

    // graph embedding appended after node embeddings
    graph_kernel<<<NB, 64>>>(out, out + Nn * 64);
}

// round 6
// speedup vs baseline: 1.6778x; 1.0549x over previous
#include <cuda_runtime.h>
#include <cuda_fp16.h>
#include <cuda_bf16.h>

// ---------------- problem constants ----------------
constexpr int NB     = 64;     // batches
constexpr int NODES_ = 116;    // nodes per batch
constexpr int Nn     = NB * NODES_;   // 7424
constexpr int Tt     = 256;
constexpr int Hh     = 32;
constexpr int Ee     = Nn * 128;      // 950272
constexpr int HID    = 64;
constexpr int BPB2   = NODES_ / 4;    // GRU blocks per batch = 29 (4 nodes/block)

typedef unsigned long long ull;

// ---------------- device scratch (no cudaMalloc allowed) ----------------
__device__ __align__(16) float d_xT[(Tt + 1) * Nn]; // transposed x (+1 pad row)
__device__ __align__(16) float d_gruH[Nn * Hh];   // GRU output
__device__ __align__(16) float d_xw[Nn * HID];    // per-layer h @ W^T (fp32, self term)
__device__ __align__(16) __half d_xwh[Nn * HID];  // fp16 copy for gathers
__device__ __align__(16) float d_hbuf[Nn * HID];  // per-layer output
__device__ float d_deg[Nn];
__device__ float d_dis[Nn];
__device__ float d_dis2[Nn];
__device__ __align__(16) int d_cnt[8192];         // padded for int4 scan loads
__device__ int   d_rowptr[Nn + 1];
__device__ int   d_cursor[Nn];
__device__ int   d_order[NB];                     // batches sorted by length desc
__device__ __align__(16) ull d_edge[Ee];          // packed (src:int lo32, coef:f32 hi32)

// ---------------- helpers ----------------
__device__ __forceinline__ float sigm_(float a) {
    return __fdividef(1.0f, 1.0f + __expf(-a));
}
__device__ __forceinline__ float tanh_(float a) {
    return fmaf(-2.0f, __fdividef(1.0f, 1.0f + __expf(2.0f * a)), 1.0f);
}
__device__ __forceinline__ ull fma2_(ull a, ull b, ull c) {
    ull d;
    asm("fma.rn.f32x2 %0, %1, %2, %3;" : "=l"(d) : "l"(a), "l"(b), "l"(c));
    return d;
}
__device__ __forceinline__ ull pack2_(float lo, float hi) {
    ull d;
    asm("mov.b64 %0, {%1, %2};" : "=l"(d) : "f"(lo), "f"(hi));
    return d;
}
__device__ __forceinline__ float hsum2_(ull v) {
    float lo, hi;
    asm("mov.b64 {%0, %1}, %2;" : "=f"(lo), "=f"(hi) : "l"(v));
    return lo + hi;
}

// ---------------- 1) transpose x [N][T]->[T][N]  (+ fused deg/cnt init) ----------------
__global__ void transpose_x_kernel(const float* __restrict__ x, float* __restrict__ xT,
                                   float* __restrict__ deg, int* __restrict__ cnt) {
    __shared__ float tile[32][33];
    int bn = blockIdx.x * 32;
    int bt = blockIdx.y * 32;
    int tx = threadIdx.x, ty = threadIdx.y; // (32, 8)
    #pragma unroll
    for (int j = 0; j < 32; j += 8)
        tile[ty + j][tx] = x[(bn + ty + j) * Tt + (bt + tx)];
    __syncthreads();
    #pragma unroll
    for (int j = 0; j < 32; j += 8)
        xT[(bt + ty + j) * Nn + (bn + tx)] = tile[tx][ty + j];
    // fused init: 1856 blocks x 256 threads covers 8192 slots
    int gid = (blockIdx.y * gridDim.x + blockIdx.x) * 256 + ty * 32 + tx;
    if (gid < 8192) {
        cnt[gid] = 0;
        if (gid < Nn) deg[gid] = 1.0f;
    }
}

// ---------------- 2) degree + in-count histogram ----------------
__global__ void edge_deg_kernel(const int* __restrict__ ei, const float* __restrict__ ea,
                                float* __restrict__ deg, int* __restrict__ cnt) {
    int e = blockIdx.x * 256 + threadIdx.x;
    if (e >= Ee) return;
    int dst = ei[Ee + e];
    atomicAdd(&deg[dst], ea[e]);
    atomicAdd(&cnt[dst], 1);
}

// ---------------- 3) scan: warp-shuffle two-level -> rowptr/cursor + dis/dis2 ----------------
__global__ void scan_kernel(const int* __restrict__ cnt, const float* __restrict__ deg,
                            int* __restrict__ rowptr, int* __restrict__ cursor,
                            float* __restrict__ dis, float* __restrict__ dis2) {
    __shared__ int swarp[32];
    int tid = threadIdx.x;          // 1024
    int wid = tid >> 5, lane = tid & 31;
    const int4* c4 = (const int4*)cnt;
    int4 v0 = c4[tid * 2];
    int4 v1 = c4[tid * 2 + 1];
    int vals[8] = {v0.x, v0.y, v0.z, v0.w, v1.x, v1.y, v1.z, v1.w};
    int loc[8];
    int s = 0;
    #pragma unroll
    for (int j = 0; j < 8; j++) { loc[j] = s; s += vals[j]; }
    // inclusive warp scan of s
    int sc = s;
    #pragma unroll
    for (int off = 1; off < 32; off <<= 1) {
        int n = __shfl_up_sync(0xffffffffu, sc, off);
        if (lane >= off) sc += n;
    }
    if (lane == 31) swarp[wid] = sc;
    __syncthreads();
    if (wid == 0) {
        int w = swarp[lane];
        #pragma unroll
        for (int off = 1; off < 32; off <<= 1) {
            int n = __shfl_up_sync(0xffffffffu, w, off);
            if (lane >= off) w += n;
        }
        swarp[lane] = w;
    }
    __syncthreads();
    int base = (wid > 0 ? swarp[wid - 1] : 0) + (sc - s);  // exclusive prefix
    int idx0 = tid * 8;
    #pragma unroll
    for (int j = 0; j < 8; j++) {
        int idx = idx0 + j;
        if (idx < Nn) {
            int v = base + loc[j];
            rowptr[idx] = v;
            cursor[idx] = v;
        }
    }
    if (tid == 1023) rowptr[Nn] = base + s;
    for (int i = tid; i < Nn; i += 1024) {
        float dg = deg[i];
        float di = rsqrtf(dg);
        dis[i]  = di;
        dis2[i] = di * di;
    }
}

// ---------------- 4) CSR fill (by dst), packed (src, coef) records  [profiled slot] ----------------
__global__ void csr_fill_kernel(const int* __restrict__ ei, const float* __restrict__ ea,
                                const float* __restrict__ dis, int* __restrict__ cursor,
                                ull* __restrict__ edge) {
    int e = blockIdx.x * 256 + threadIdx.x;
    if (e >= Ee) return;
    int src = ei[e];
    int dst = ei[Ee + e];
    float c = dis[src] * ea[e] * dis[dst];
    int pos = atomicAdd(&cursor[dst], 1);
    edge[pos] = ((ull)__float_as_uint(c) << 32) | (unsigned)src;
}

// ---------------- 5) sort batches by length (descending) for LPT scheduling ----------------
__global__ void sort_kernel(const int* __restrict__ lengths, int* __restrict__ order) {
    __shared__ int sl[NB];
    int l = threadIdx.x;     // 64
    int v = lengths[l];
    sl[l] = v;
    __syncthreads();
    int r = 0;
    #pragma unroll
    for (int m = 0; m < NB; m++) {
        int vm = sl[m];
        r += (vm > v) || (vm == v && m < l);
    }
    order[r] = l;
}

// ---------------- 6) GRU: 2 nodes per warp, 1 channel per thread ----------------
// Register-resident packed weights shared across both nodes; two independent
// dependency chains per warp hide the LDS/activation latency tail.
__global__ void __launch_bounds__(64) gru_kernel(
    const float* __restrict__ xT, const int* __restrict__ lengths,
    const int* __restrict__ order,
    const float* __restrict__ W_hh, const float* __restrict__ W_ih,
    const float* __restrict__ b_ih, const float* __restrict__ b_hh,
    float* __restrict__ out) {
    __shared__ __align__(16) float sh_h[2][4][32];   // [buf][node-in-block][channel]
    int tid = threadIdx.x;
    int wid = tid >> 5;          // warp id (2 warps/block)
    int j   = tid & 31;          // hidden channel
    int batch = order[blockIdx.x / BPB2];
    int n0 = batch * NODES_ + (blockIdx.x % BPB2) * 4 + wid * 2;  // nodes n0, n0+1
    int len = lengths[batch];    // uniform across warp

    // one-time weight load into registers: 16 packed k-pairs per gate (shared by both nodes)
    ull wR[16], wZ[16], wN[16];
    #pragma unroll
    for (int p = 0; p < 16; p++) {
        wR[p] = *(const ull*)&W_hh[(j     ) * 32 + 2 * p];
        wZ[p] = *(const ull*)&W_hh[(32 + j) * 32 + 2 * p];
        wN[p] = *(const ull*)&W_hh[(64 + j) * 32 + 2 * p];
    }
    float wiR = W_ih[j], wiZ = W_ih[32 + j], wiN = W_ih[64 + j];
    float bR  = b_ih[j]      + b_hh[j];
    float bZ  = b_ih[32 + j] + b_hh[32 + j];
    float bNx = b_ih[64 + j];
    float bNh = b_hh[64 + j];

    int ra = wid * 2, rb = wid * 2 + 1;
    float h0 = 0.0f, h1 = 0.0f;
    sh_h[0][ra][j] = 0.0f;
    sh_h[0][rb][j] = 0.0f;
    __syncwarp();

    const longlong2* hrdA = (const longlong2*)sh_h[0][ra];
    const longlong2* hrdB = (const longlong2*)sh_h[0][rb];
    float* hwrA = sh_h[1][ra];
    float* hwrB = sh_h[1][rb];

    const float* xp = xT + n0;
    float2 xv = *(const float2*)xp;   // broadcast LDG.64: x for both nodes
    xp += Nn;
    for (int t = 0; t < len; t++) {
        float xt0 = xv.x, xt1 = xv.y;
        xv = *(const float2*)xp;      // row t+1 (pad row Tt on final iter)
        xp += Nn;

        ull aR0 = pack2_(fmaf(xt0, wiR, bR), 0.0f);
        ull aZ0 = pack2_(fmaf(xt0, wiZ, bZ), 0.0f);
        ull aN0 = pack2_(bNh, 0.0f);
        ull aR1 = pack2_(fmaf(xt1, wiR, bR), 0.0f);
        ull aZ1 = pack2_(fmaf(xt1, wiZ, bZ), 0.0f);
        ull aN1 = pack2_(bNh, 0.0f);
        #pragma unroll
        for (int p = 0; p < 8; p++) {
            longlong2 ha = hrdA[p];          // broadcast LDS.128: 4 h of node 0
            longlong2 hb = hrdB[p];          // broadcast LDS.128: 4 h of node 1
            ull a0 = (ull)ha.x, a1 = (ull)ha.y;
            ull b0 = (ull)hb.x, b1 = (ull)hb.y;
            aR0 = fma2_(a0, wR[2 * p], aR0);
            aR1 = fma2_(b0, wR[2 * p], aR1);
            aZ0 = fma2_(a0, wZ[2 * p], aZ0);
            aZ1 = fma2_(b0, wZ[2 * p], aZ1);
            aN0 = fma2_(a0, wN[2 * p], aN0);
            aN1 = fma2_(b0, wN[2 * p], aN1);
            aR0 = fma2_(a1, wR[2 * p + 1], aR0);
            aR1 = fma2_(b1, wR[2 * p + 1], aR1);
            aZ0 = fma2_(a1, wZ[2 * p + 1], aZ0);
            aZ1 = fma2_(b1, wZ[2 * p + 1], aZ1);
            aN0 = fma2_(a1, wN[2 * p + 1], aN0);
            aN1 = fma2_(b1, wN[2 * p + 1], aN1);
        }
        float r0 = sigm_(hsum2_(aR0));
        float r1 = sigm_(hsum2_(aR1));
        float z0 = sigm_(hsum2_(aZ0));
        float z1 = sigm_(hsum2_(aZ1));
        float nn0 = tanh_(fmaf(xt0, wiN, bNx) + r0 * hsum2_(aN0));
        float nn1 = tanh_(fmaf(xt1, wiN, bNx) + r1 * hsum2_(aN1));
        h0 = fmaf(z0, h0 - nn0, nn0);        // (1-z)*nn + z*h
        h1 = fmaf(z1, h1 - nn1, nn1);
        hwrA[j] = h0;
        hwrB[j] = h1;
        __syncwarp();
        float* tA = (float*)hrdA; hrdA = (const longlong2*)hwrA; hwrA = tA;
        float* tB = (float*)hrdB; hrdB = (const longlong2*)hwrB; hwrB = tB;
    }
    out[n0 * Hh + j]       = h0;
    out[(n0 + 1) * Hh + j] = h1;
}

// ---------------- 7) GEMM: out[n][o] = sum_k in[n][k] * W[o][k]; also fp16 copy ----------------
template <int Kd>
__global__ void gemm_kernel(const float* __restrict__ in, const float* __restrict__ W,
                            float* __restrict__ out, __half* __restrict__ outh) {
    __shared__ float sW[Kd * 64]; // [k][o]
    __shared__ float sh[4 * Kd];
    int tid = threadIdx.x; // 256
    for (int i = tid; i < Kd * 64; i += 256) {
        int k = i >> 6, o = i & 63;
        sW[i] = W[o * Kd + k];
    }
    int nb = blockIdx.x * 4;
    for (int i = tid; i < 4 * Kd; i += 256)
        sh[i] = in[nb * Kd + i];
    __syncthreads();
    int ln = tid >> 6, o = tid & 63;
    float acc = 0.0f;
    #pragma unroll
    for (int k = 0; k < Kd; k++)
        acc = fmaf(sh[ln * Kd + k], sW[k * 64 + o], acc);
    out[(nb + ln) * 64 + o]  = acc;
    outh[(nb + ln) * 64 + o] = __float2half(acc);
}

// ---------------- 8) aggregation: fp16 gather over dst-CSR + fp32 self + bias + PReLU ----------------
__global__ void agg_kernel(const float* __restrict__ xw, const __half* __restrict__ xwh,
                           const float* __restrict__ dis2,
                           const int* __restrict__ rowptr, const ull* __restrict__ edge,
                           const float* __restrict__ bias,
                           const float* __restrict__ prelu_a, int layer,
                           float* __restrict__ out) {
    int tid = threadIdx.x;           // 128 -> 8 nodes per block, 16 lanes per node
    int n = blockIdx.x * 8 + (tid >> 4);
    int l = tid & 15;
    int lane = tid & 31;
    unsigned gmask = 0xFFFFu << (lane & 16);

    const float4* __restrict__ xw4 = (const float4*)xw;
    const uint2* __restrict__ xh = (const uint2*)xwh;   // 4 halves per element
    float4 acc = xw4[n * 16 + l];
    float d2 = dis2[n];
    acc.x *= d2; acc.y *= d2; acc.z *= d2; acc.w *= d2;

    int e0 = rowptr[n], e1 = rowptr[n + 1];
    for (int e = e0; e < e1; e += 16) {
        ull rec = 0;                              // zero coef pads partial chunks
        if (e + l < e1) rec = edge[e + l];
        #pragma unroll
        for (int m = 0; m < 16; m++) {
            ull rm = __shfl_sync(gmask, rec, m, 16);
            int   sm = (int)(unsigned)rm;
            float cm = __uint_as_float((unsigned)(rm >> 32));
            uint2 hv = xh[sm * 16 + l];
            float2 f0 = __half22float2(*(__half2*)&hv.x);
            float2 f1 = __half22float2(*(__half2*)&hv.y);
            acc.x = fmaf(cm, f0.x, acc.x); acc.y = fmaf(cm, f0.y, acc.y);
            acc.z = fmaf(cm, f1.x, acc.z); acc.w = fmaf(cm, f1.y, acc.w);
        }
    }
    float4 b4 = ((const float4*)bias)[l];
    acc.x += b4.x; acc.y += b4.y; acc.z += b4.z; acc.w += b4.w;
    float a = prelu_a[layer];
    acc.x = (acc.x >= 0.f) ? acc.x : a * acc.x;
    acc.y = (acc.y >= 0.f) ? acc.y : a * acc.y;
    acc.z = (acc.z >= 0.f) ? acc.z : a * acc.z;
    acc.w = (acc.w >= 0.f) ? acc.w : a * acc.w;
    ((float4*)out)[n * 16 + l] = acc;
}

// ---------------- 9) graph mean pooling ----------------
__global__ void graph_kernel(const float* __restrict__ node_emb, float* __restrict__ gout) {
    int b = blockIdx.x;   // 64
    int d = threadIdx.x;  // 64
    float s = 0.0f;
    #pragma unroll 8
    for (int i = 0; i < NODES_; i++)
        s += node_emb[(b * NODES_ + i) * 64 + d];
    gout[b * 64 + d] = s * (1.0f / (float)NODES_);
}

// ---------------- launch ----------------
extern "C" void kernel_launch(void* const* d_in, const int* in_sizes, int n_in,
                              void* d_out, int out_size) {
    const float* x       = (const float*)d_in[0];
    const int*   ei      = (const int*)d_in[1];
    const float* ea      = (const float*)d_in[2];
    const int*   lengths = (const int*)d_in[3];
    // d_in[4] = batch (unused; batch[n] == n / NODES_)
    const float* W_ih    = (const float*)d_in[5];
    const float* W_hh    = (const float*)d_in[6];
    const float* b_ih    = (const float*)d_in[7];
    const float* b_hh    = (const float*)d_in[8];
    const float* g_w0    = (const float*)d_in[9];
    const float* g_b0    = (const float*)d_in[10];
    const float* g_ws    = (const float*)d_in[11];
    const float* g_bs    = (const float*)d_in[12];
    const float* prelu_a = (const float*)d_in[13];
    float* out = (float*)d_out;

    float *xT, *gruH, *xw, *hbuf, *deg, *dis, *dis2;
    __half* xwh;
    int *cnt, *rowptr, *cursor, *order;
    ull* edge;
    cudaGetSymbolAddress((void**)&xT,     d_xT);
    cudaGetSymbolAddress((void**)&gruH,   d_gruH);
    cudaGetSymbolAddress((void**)&xw,     d_xw);
    cudaGetSymbolAddress((void**)&xwh,    d_xwh);
    cudaGetSymbolAddress((void**)&hbuf,   d_hbuf);
    cudaGetSymbolAddress((void**)&deg,    d_deg);
    cudaGetSymbolAddress((void**)&dis,    d_dis);
    cudaGetSymbolAddress((void**)&dis2,   d_dis2);
    cudaGetSymbolAddress((void**)&cnt,    d_cnt);
    cudaGetSymbolAddress((void**)&rowptr, d_rowptr);
    cudaGetSymbolAddress((void**)&cursor, d_cursor);
    cudaGetSymbolAddress((void**)&order,  d_order);
    cudaGetSymbolAddress((void**)&edge,   d_edge);

    // 1: transpose (+deg/cnt init)
    transpose_x_kernel<<<dim3(Nn / 32, Tt / 32), dim3(32, 8)>>>(x, xT, deg, cnt);
    // 2: degree + count histogram
    edge_deg_kernel<<<Ee / 256, 256>>>(ei, ea, deg, cnt);
    // 3: scan
    scan_kernel<<<1, 1024>>>(cnt, deg, rowptr, cursor, dis, dis2);
    // 4: CSR fill  (profiled slot)
    csr_fill_kernel<<<Ee / 256, 256>>>(ei, ea, dis, cursor, edge);
    // 5: LPT batch order
    sort_kernel<<<1, NB>>>(lengths, order);
    // 6: GRU (2 nodes per warp)
    gru_kernel<<<NB * BPB2, 64>>>(xT, lengths, order, W_hh, W_ih, b_ih, b_hh, gruH);

    // GCN layers
    gemm_kernel<32><<<Nn / 4, 256>>>(gruH, g_w0, xw, xwh);
    agg_kernel<<<Nn / 8, 128>>>(xw, xwh, dis2, rowptr, edge, g_b0, prelu_a, 0, hbuf);
    for (int i = 1; i < 4; i++) {
        gemm_kernel<64><<<Nn / 4, 256>>>(hbuf, g_ws + (i - 1) * 64 * 64, xw, xwh);
        float* dst = (i == 3) ? out : hbuf;
        agg_kernel<<<Nn / 8, 128>>>(xw, xwh, dis2, rowptr, edge,
                                    g_bs + (i - 1) * 64, prelu_a, i, dst);
    }

    // graph embedding appended after node embeddings
    graph_kernel<<<NB, 64>>>(out, out + Nn * 64);
}

// round 8
// speedup vs baseline: 1.7540x; 1.0454x over previous
#include <cuda_runtime.h>
#include <cuda_fp16.h>
#include <cuda_bf16.h>

// ---------------- problem constants ----------------
constexpr int NB     = 64;     // batches
constexpr int NODES_ = 116;    // nodes per batch
constexpr int Nn     = NB * NODES_;   // 7424
constexpr int Tt     = 256;
constexpr int Hh     = 32;
constexpr int Ee     = Nn * 128;      // 950272
constexpr int HID    = 64;
constexpr int BPB2   = NODES_ / 4;    // GRU blocks per batch = 29 (4 nodes/block)
constexpr int NGRUB  = NB * BPB2;     // 1856 GRU blocks
constexpr int NTRB   = (Nn / 32) * (Tt / 32);  // 1856 transpose blocks
constexpr int NEDB   = Ee / 256;      // 3712 edge_deg blocks
constexpr int NCSRB  = Ee / 64;       // 14848 csr blocks (64 thr each)

typedef unsigned long long ull;

// ---------------- device scratch (no cudaMalloc allowed) ----------------
__device__ __align__(16) float d_xT[(Tt + 1) * Nn]; // transposed x (+1 pad row)
__device__ __align__(16) float d_gruH[Nn * Hh];   // GRU output
__device__ __align__(16) float d_xw[Nn * HID];    // per-layer h @ W^T (fp32, self term)
__device__ __align__(16) __half d_xwh[Nn * HID];  // fp16 copy for gathers
__device__ __align__(16) float d_hbuf[Nn * HID];  // per-layer output
__device__ float d_deg[Nn];
__device__ float d_dis[Nn];
__device__ float d_dis2[Nn];
__device__ __align__(16) int d_cnt[8192];         // padded for int4 scan loads
__device__ int   d_rowptr[Nn + 1];
__device__ int   d_cursor[Nn];
__device__ int   d_order[NB];                     // batches sorted by length desc
__device__ __align__(16) ull d_edge[Ee];          // packed (src:int lo32, coef:f32 hi32)

// ---------------- helpers ----------------
__device__ __forceinline__ float sigm_(float a) {
    return __fdividef(1.0f, 1.0f + __expf(-a));
}
__device__ __forceinline__ float tanh_(float a) {
    return fmaf(-2.0f, __fdividef(1.0f, 1.0f + __expf(2.0f * a)), 1.0f);
}
__device__ __forceinline__ ull fma2_(ull a, ull b, ull c) {
    ull d;
    asm("fma.rn.f32x2 %0, %1, %2, %3;" : "=l"(d) : "l"(a), "l"(b), "l"(c));
    return d;
}
__device__ __forceinline__ ull pack2_(float lo, float hi) {
    ull d;
    asm("mov.b64 %0, {%1, %2};" : "=l"(d) : "f"(lo), "f"(hi));
    return d;
}
__device__ __forceinline__ float hsum2_(ull v) {
    float lo, hi;
    asm("mov.b64 {%0, %1}, %2;" : "=f"(lo), "=f"(hi) : "l"(v));
    return lo + hi;
}

// ---------------- 1) init deg/cnt ----------------
__global__ void init_kernel(float* __restrict__ deg, int* __restrict__ cnt) {
    int i = blockIdx.x * 256 + threadIdx.x;
    if (i < Nn) deg[i] = 1.0f;
    if (i < 8192) cnt[i] = 0;
}

// ---------------- 2) fused: transpose | edge_deg | sort (block-range partition) ----------------
__global__ void __launch_bounds__(256) fused_pre_kernel(
    const float* __restrict__ x, float* __restrict__ xT,
    const int* __restrict__ ei, const float* __restrict__ ea,
    float* __restrict__ deg, int* __restrict__ cnt,
    const int* __restrict__ lengths, int* __restrict__ order) {
    int bid = blockIdx.x;
    int tid = threadIdx.x;
    if (bid < NTRB) {
        // transpose x [N][T] -> [T][N]
        __shared__ float tile[32][33];
        int bx = bid % (Nn / 32), by = bid / (Nn / 32);
        int bn = bx * 32, bt = by * 32;
        int tx = tid & 31, ty = tid >> 5;   // (32, 8)
        #pragma unroll
        for (int j = 0; j < 32; j += 8)
            tile[ty + j][tx] = x[(bn + ty + j) * Tt + (bt + tx)];
        __syncthreads();
        #pragma unroll
        for (int j = 0; j < 32; j += 8)
            xT[(bt + ty + j) * Nn + (bn + tx)] = tile[tx][ty + j];
    } else if (bid < NTRB + NEDB) {
        // degree + in-count histogram
        int e = (bid - NTRB) * 256 + tid;
        int dst = ei[Ee + e];
        atomicAdd(&deg[dst], ea[e]);
        atomicAdd(&cnt[dst], 1);
    } else {
        // rank-sort batches by length (descending)
        __shared__ int sl[NB];
        if (tid < NB) sl[tid] = lengths[tid];
        __syncthreads();
        if (tid < NB) {
            int v = sl[tid];
            int r = 0;
            #pragma unroll
            for (int m = 0; m < NB; m++) {
                int vm = sl[m];
                r += (vm > v) || (vm == v && m < tid);
            }
            order[r] = tid;
        }
    }
}

// ---------------- 3) scan: warp-shuffle two-level -> rowptr/cursor + dis/dis2 ----------------
__global__ void scan_kernel(const int* __restrict__ cnt, const float* __restrict__ deg,
                            int* __restrict__ rowptr, int* __restrict__ cursor,
                            float* __restrict__ dis, float* __restrict__ dis2) {
    __shared__ int swarp[32];
    int tid = threadIdx.x;          // 1024
    int wid = tid >> 5, lane = tid & 31;
    const int4* c4 = (const int4*)cnt;
    int4 v0 = c4[tid * 2];
    int4 v1 = c4[tid * 2 + 1];
    int vals[8] = {v0.x, v0.y, v0.z, v0.w, v1.x, v1.y, v1.z, v1.w};
    int loc[8];
    int s = 0;
    #pragma unroll
    for (int j = 0; j < 8; j++) { loc[j] = s; s += vals[j]; }
    int sc = s;
    #pragma unroll
    for (int off = 1; off < 32; off <<= 1) {
        int n = __shfl_up_sync(0xffffffffu, sc, off);
        if (lane >= off) sc += n;
    }
    if (lane == 31) swarp[wid] = sc;
    __syncthreads();
    if (wid == 0) {
        int w = swarp[lane];
        #pragma unroll
        for (int off = 1; off < 32; off <<= 1) {
            int n = __shfl_up_sync(0xffffffffu, w, off);
            if (lane >= off) w += n;
        }
        swarp[lane] = w;
    }
    __syncthreads();
    int base = (wid > 0 ? swarp[wid - 1] : 0) + (sc - s);  // exclusive prefix
    int idx0 = tid * 8;
    #pragma unroll
    for (int j = 0; j < 8; j++) {
        int idx = idx0 + j;
        if (idx < Nn) {
            int v = base + loc[j];
            rowptr[idx] = v;
            cursor[idx] = v;
        }
    }
    if (tid == 1023) rowptr[Nn] = base + s;
    for (int i = tid; i < Nn; i += 1024) {
        float dg = deg[i];
        float di = rsqrtf(dg);
        dis[i]  = di;
        dis2[i] = di * di;
    }
}

// ---------------- 4) merged: GRU (bids 0..NGRUB-1) | CSR fill (rest)  ----------------
// GRU: 2 nodes per warp, register-resident packed weights, double-buffered h row.
// CSR fill blocks backfill the GRU's drain tail (latency-bound, hides in stalls).
__global__ void __launch_bounds__(64) gru_csr_kernel(
    const float* __restrict__ xT, const int* __restrict__ lengths,
    const int* __restrict__ order,
    const float* __restrict__ W_hh, const float* __restrict__ W_ih,
    const float* __restrict__ b_ih, const float* __restrict__ b_hh,
    float* __restrict__ out,
    const int* __restrict__ ei, const float* __restrict__ ea,
    const float* __restrict__ dis, int* __restrict__ cursor,
    ull* __restrict__ edge) {
    int bid = blockIdx.x;
    int tid = threadIdx.x;
    if (bid >= NGRUB) {
        // ---- CSR fill: one edge per thread ----
        int e = (bid - NGRUB) * 64 + tid;
        int src = ei[e];
        int dst = ei[Ee + e];
        float c = dis[src] * ea[e] * dis[dst];
        int pos = atomicAdd(&cursor[dst], 1);
        edge[pos] = ((ull)__float_as_uint(c) << 32) | (unsigned)src;
        return;
    }
    // ---- GRU ----
    __shared__ __align__(16) float sh_h[2][4][32];   // [buf][node-in-block][channel]
    int wid = tid >> 5;          // warp id (2 warps/block)
    int j   = tid & 31;          // hidden channel
    int batch = order[bid / BPB2];
    int n0 = batch * NODES_ + (bid % BPB2) * 4 + wid * 2;  // nodes n0, n0+1
    int len = lengths[batch];    // uniform across warp

    ull wR[16], wZ[16], wN[16];
    #pragma unroll
    for (int p = 0; p < 16; p++) {
        wR[p] = *(const ull*)&W_hh[(j     ) * 32 + 2 * p];
        wZ[p] = *(const ull*)&W_hh[(32 + j) * 32 + 2 * p];
        wN[p] = *(const ull*)&W_hh[(64 + j) * 32 + 2 * p];
    }
    float wiR = W_ih[j], wiZ = W_ih[32 + j], wiN = W_ih[64 + j];
    float bR  = b_ih[j]      + b_hh[j];
    float bZ  = b_ih[32 + j] + b_hh[32 + j];
    float bNx = b_ih[64 + j];
    float bNh = b_hh[64 + j];

    int ra = wid * 2, rb = wid * 2 + 1;
    float h0 = 0.0f, h1 = 0.0f;
    sh_h[0][ra][j] = 0.0f;
    sh_h[0][rb][j] = 0.0f;
    __syncwarp();

    const longlong2* hrdA = (const longlong2*)sh_h[0][ra];
    const longlong2* hrdB = (const longlong2*)sh_h[0][rb];
    float* hwrA = sh_h[1][ra];
    float* hwrB = sh_h[1][rb];

    const float* xp = xT + n0;
    float2 xv = *(const float2*)xp;   // broadcast LDG.64: x for both nodes
    xp += Nn;
    for (int t = 0; t < len; t++) {
        float xt0 = xv.x, xt1 = xv.y;
        xv = *(const float2*)xp;      // row t+1 (pad row Tt on final iter)
        xp += Nn;

        ull aR0 = pack2_(fmaf(xt0, wiR, bR), 0.0f);
        ull aZ0 = pack2_(fmaf(xt0, wiZ, bZ), 0.0f);
        ull aN0 = pack2_(bNh, 0.0f);
        ull aR1 = pack2_(fmaf(xt1, wiR, bR), 0.0f);
        ull aZ1 = pack2_(fmaf(xt1, wiZ, bZ), 0.0f);
        ull aN1 = pack2_(bNh, 0.0f);
        #pragma unroll
        for (int p = 0; p < 8; p++) {
            longlong2 ha = hrdA[p];          // broadcast LDS.128: 4 h of node 0
            longlong2 hb = hrdB[p];          // broadcast LDS.128: 4 h of node 1
            ull a0 = (ull)ha.x, a1 = (ull)ha.y;
            ull b0 = (ull)hb.x, b1 = (ull)hb.y;
            aR0 = fma2_(a0, wR[2 * p], aR0);
            aR1 = fma2_(b0, wR[2 * p], aR1);
            aZ0 = fma2_(a0, wZ[2 * p], aZ0);
            aZ1 = fma2_(b0, wZ[2 * p], aZ1);
            aN0 = fma2_(a0, wN[2 * p], aN0);
            aN1 = fma2_(b0, wN[2 * p], aN1);
            aR0 = fma2_(a1, wR[2 * p + 1], aR0);
            aR1 = fma2_(b1, wR[2 * p + 1], aR1);
            aZ0 = fma2_(a1, wZ[2 * p + 1], aZ0);
            aZ1 = fma2_(b1, wZ[2 * p + 1], aZ1);
            aN0 = fma2_(a1, wN[2 * p + 1], aN0);
            aN1 = fma2_(b1, wN[2 * p + 1], aN1);
        }
        float r0 = sigm_(hsum2_(aR0));
        float r1 = sigm_(hsum2_(aR1));
        float z0 = sigm_(hsum2_(aZ0));
        float z1 = sigm_(hsum2_(aZ1));
        float nn0 = tanh_(fmaf(xt0, wiN, bNx) + r0 * hsum2_(aN0));
        float nn1 = tanh_(fmaf(xt1, wiN, bNx) + r1 * hsum2_(aN1));
        h0 = fmaf(z0, h0 - nn0, nn0);        // (1-z)*nn + z*h
        h1 = fmaf(z1, h1 - nn1, nn1);
        hwrA[j] = h0;
        hwrB[j] = h1;
        __syncwarp();
        float* tA = (float*)hrdA; hrdA = (const longlong2*)hwrA; hwrA = tA;
        float* tB = (float*)hrdB; hrdB = (const longlong2*)hwrB; hwrB = tB;
    }
    out[n0 * Hh + j]       = h0;
    out[(n0 + 1) * Hh + j] = h1;
}

// ---------------- GEMM: out[n][o] = sum_k in[n][k] * W[o][k]; also fp16 copy ----------------
template <int Kd>
__global__ void gemm_kernel(const float* __restrict__ in, const float* __restrict__ W,
                            float* __restrict__ out, __half* __restrict__ outh) {
    __shared__ float sW[Kd * 64]; // [k][o]
    __shared__ float sh[4 * Kd];
    int tid = threadIdx.x; // 256
    for (int i = tid; i < Kd * 64; i += 256) {
        int k = i >> 6, o = i & 63;
        sW[i] = W[o * Kd + k];
    }
    int nb = blockIdx.x * 4;
    for (int i = tid; i < 4 * Kd; i += 256)
        sh[i] = in[nb * Kd + i];
    __syncthreads();
    int ln = tid >> 6, o = tid & 63;
    float acc = 0.0f;
    #pragma unroll
    for (int k = 0; k < Kd; k++)
        acc = fmaf(sh[ln * Kd + k], sW[k * 64 + o], acc);
    out[(nb + ln) * 64 + o]  = acc;
    outh[(nb + ln) * 64 + o] = __float2half(acc);
}

// ---------------- aggregation: fp16 gather over dst-CSR + fp32 self + bias + PReLU ----------------
__global__ void agg_kernel(const float* __restrict__ xw, const __half* __restrict__ xwh,
                           const float* __restrict__ dis2,
                           const int* __restrict__ rowptr, const ull* __restrict__ edge,
                           const float* __restrict__ bias,
                           const float* __restrict__ prelu_a, int layer,
                           float* __restrict__ out) {
    int tid = threadIdx.x;           // 128 -> 8 nodes per block, 16 lanes per node
    int n = blockIdx.x * 8 + (tid >> 4);
    int l = tid & 15;
    int lane = tid & 31;
    unsigned gmask = 0xFFFFu << (lane & 16);

    const float4* __restrict__ xw4 = (const float4*)xw;
    const uint2* __restrict__ xh = (const uint2*)xwh;   // 4 halves per element
    float4 acc = xw4[n * 16 + l];
    float d2 = dis2[n];
    acc.x *= d2; acc.y *= d2; acc.z *= d2; acc.w *= d2;

    int e0 = rowptr[n], e1 = rowptr[n + 1];
    for (int e = e0; e < e1; e += 16) {
        ull rec = 0;                              // zero coef pads partial chunks
        if (e + l < e1) rec = edge[e + l];
        #pragma unroll
        for (int m = 0; m < 16; m++) {
            ull rm = __shfl_sync(gmask, rec, m, 16);
            int   sm = (int)(unsigned)rm;
            float cm = __uint_as_float((unsigned)(rm >> 32));
            uint2 hv = xh[sm * 16 + l];
            float2 f0 = __half22float2(*(__half2*)&hv.x);
            float2 f1 = __half22float2(*(__half2*)&hv.y);
            acc.x = fmaf(cm, f0.x, acc.x); acc.y = fmaf(cm, f0.y, acc.y);
            acc.z = fmaf(cm, f1.x, acc.z); acc.w = fmaf(cm, f1.y, acc.w);
        }
    }
    float4 b4 = ((const float4*)bias)[l];
    acc.x += b4.x; acc.y += b4.y; acc.z += b4.z; acc.w += b4.w;
    float a = prelu_a[layer];
    acc.x = (acc.x >= 0.f) ? acc.x : a * acc.x;
    acc.y = (acc.y >= 0.f) ? acc.y : a * acc.y;
    acc.z = (acc.z >= 0.f) ? acc.z : a * acc.z;
    acc.w = (acc.w >= 0.f) ? acc.w : a * acc.w;
    ((float4*)out)[n * 16 + l] = acc;
}

// ---------------- graph mean pooling ----------------
__global__ void graph_kernel(const float* __restrict__ node_emb, float* __restrict__ gout) {
    int b = blockIdx.x;   // 64
    int d = threadIdx.x;  // 64
    float s = 0.0f;
    #pragma unroll 8
    for (int i = 0; i < NODES_; i++)
        s += node_emb[(b * NODES_ + i) * 64 + d];
    gout[b * 64 + d] = s * (1.0f / (float)NODES_);
}

// ---------------- launch (single stream; overlap via fused grid partitions) ----------------
extern "C" void kernel_launch(void* const* d_in, const int* in_sizes, int n_in,
                              void* d_out, int out_size) {
    const float* x       = (const float*)d_in[0];
    const int*   ei      = (const int*)d_in[1];
    const float* ea      = (const float*)d_in[2];
    const int*   lengths = (const int*)d_in[3];
    // d_in[4] = batch (unused; batch[n] == n / NODES_)
    const float* W_ih    = (const float*)d_in[5];
    const float* W_hh    = (const float*)d_in[6];
    const float* b_ih    = (const float*)d_in[7];
    const float* b_hh    = (const float*)d_in[8];
    const float* g_w0    = (const float*)d_in[9];
    const float* g_b0    = (const float*)d_in[10];
    const float* g_ws    = (const float*)d_in[11];
    const float* g_bs    = (const float*)d_in[12];
    const float* prelu_a = (const float*)d_in[13];
    float* out = (float*)d_out;

    float *xT, *gruH, *xw, *hbuf, *deg, *dis, *dis2;
    __half* xwh;
    int *cnt, *rowptr, *cursor, *order;
    ull* edge;
    cudaGetSymbolAddress((void**)&xT,     d_xT);
    cudaGetSymbolAddress((void**)&gruH,   d_gruH);
    cudaGetSymbolAddress((void**)&xw,     d_xw);
    cudaGetSymbolAddress((void**)&xwh,    d_xwh);
    cudaGetSymbolAddress((void**)&hbuf,   d_hbuf);
    cudaGetSymbolAddress((void**)&deg,    d_deg);
    cudaGetSymbolAddress((void**)&dis,    d_dis);
    cudaGetSymbolAddress((void**)&dis2,   d_dis2);
    cudaGetSymbolAddress((void**)&cnt,    d_cnt);
    cudaGetSymbolAddress((void**)&rowptr, d_rowptr);
    cudaGetSymbolAddress((void**)&cursor, d_cursor);
    cudaGetSymbolAddress((void**)&order,  d_order);
    cudaGetSymbolAddress((void**)&edge,   d_edge);

    // 1: init deg/cnt
    init_kernel<<<8192 / 256, 256>>>(deg, cnt);
    // 2: fused transpose | edge_deg | sort
    fused_pre_kernel<<<NTRB + NEDB + 1, 256>>>(x, xT, ei, ea, deg, cnt, lengths, order);
    // 3: scan -> rowptr/cursor/dis
    scan_kernel<<<1, 1024>>>(cnt, deg, rowptr, cursor, dis, dis2);
    // 4: merged GRU | CSR fill  (profiled slot)
    gru_csr_kernel<<<NGRUB + NCSRB, 64>>>(xT, lengths, order, W_hh, W_ih, b_ih, b_hh,
                                          gruH, ei, ea, dis, cursor, edge);

    // GCN layers
    gemm_kernel<32><<<Nn / 4, 256>>>(gruH, g_w0, xw, xwh);
    agg_kernel<<<Nn / 8, 128>>>(xw, xwh, dis2, rowptr, edge, g_b0, prelu_a, 0, hbuf);
    for (int i = 1; i < 4; i++) {
        gemm_kernel<64><<<Nn / 4, 256>>>(hbuf, g_ws + (i - 1) * 64 * 64, xw, xwh);
        float* dst = (i == 3) ? out : hbuf;
        agg_kernel<<<Nn / 8, 128>>>(xw, xwh, dis2, rowptr, edge,
                                    g_bs + (i - 1) * 64, prelu_a, i, dst);
    }

    // graph embedding appended after node embeddings
    graph_kernel<<<NB, 64>>>(out, out + Nn * 64);
}